// round 13
// baseline (speedup 1.0000x reference)
#include <cuda_runtime.h>
#include <cuda_bf16.h>
#include <cstdint>

using bf16 = __nv_bfloat16;
#define TT 1024
#define HS 1048576
#define ATT_SCALE 0.125f

__device__ float g_wraw[TT*4096];
__device__ float g_betah[32*TT];
__device__ float g_rhs[32*HS];      // solve rhs, later attn split-K scratch

__device__ bf16 g_xh[1048576],  g_xl[1048576];
__device__ bf16 g_qwh[1048576], g_qwl[1048576];
__device__ bf16 g_kwh[1048576], g_kwl[1048576];
__device__ bf16 g_vwh[1048576], g_vwl[1048576];
__device__ bf16 g_owh[2097152], g_owl[2097152];
__device__ bf16 g_w2h[131072],  g_w2l[131072];
__device__ bf16 g_wlh[32768],   g_wll[32768];
__device__ bf16 g_qh[1048576],  g_ql[1048576];
__device__ bf16 g_kh[1048576],  g_kl[1048576];
__device__ bf16 g_knh[1048576], g_knl[1048576];
__device__ bf16 g_vh[1048576],  g_vl[1048576];
__device__ bf16 g_wdh[2097152], g_wdl[2097152];
__device__ bf16 g_Mwh[33554432], g_Mwl[33554432];
__device__ bf16 g_Bh [33554432], g_Bl [33554432];
__device__ bf16 g_QWh[33554432], g_QWl[33554432];
__device__ bf16 g_Tvh[2097152],  g_Tvl[2097152];
__device__ bf16 g_O2h[2097152],  g_O2l[2097152];

__device__ __forceinline__ uint32_t sptr(const void* p) {
    return (uint32_t)__cvta_generic_to_shared(p);
}
__device__ __forceinline__ void ldsm4(uint32_t* r, uint32_t a) {
    asm volatile("ldmatrix.sync.aligned.m8n8.x4.shared.b16 {%0,%1,%2,%3}, [%4];"
        : "=r"(r[0]), "=r"(r[1]), "=r"(r[2]), "=r"(r[3]) : "r"(a));
}
__device__ __forceinline__ void ldsm4t(uint32_t* r, uint32_t a) {
    asm volatile("ldmatrix.sync.aligned.m8n8.x4.trans.shared.b16 {%0,%1,%2,%3}, [%4];"
        : "=r"(r[0]), "=r"(r[1]), "=r"(r[2]), "=r"(r[3]) : "r"(a));
}
__device__ __forceinline__ void mma_bf(float* c, const uint32_t* a, const uint32_t* b) {
    asm volatile(
        "mma.sync.aligned.m16n8k16.row.col.f32.bf16.bf16.f32 "
        "{%0,%1,%2,%3},{%4,%5,%6,%7},{%8,%9},{%0,%1,%2,%3};"
        : "+f"(c[0]), "+f"(c[1]), "+f"(c[2]), "+f"(c[3])
        : "r"(a[0]), "r"(a[1]), "r"(a[2]), "r"(a[3]), "r"(b[0]), "r"(b[1]));
}
__device__ __forceinline__ void st_split2(bf16* hi, bf16* lo, size_t off, float v0, float v1) {
    bf16 h0 = __float2bfloat16(v0), h1 = __float2bfloat16(v1);
    *(__nv_bfloat162*)(hi + off) = __halves2bfloat162(h0, h1);
    *(__nv_bfloat162*)(lo + off) = __halves2bfloat162(
        __float2bfloat16(v0 - __bfloat162float(h0)),
        __float2bfloat16(v1 - __bfloat162float(h1)));
}
__device__ __forceinline__ void cpa16(void* s, const void* g) {
    asm volatile("cp.async.cg.shared.global [%0], [%1], 16;" :: "r"(sptr(s)), "l"(g) : "memory");
}
#define CPC() asm volatile("cp.async.commit_group;" ::: "memory")
#define CPW(n) asm volatile("cp.async.wait_group %0;" :: "n"(n) : "memory")

template<bool TRANSB>
__device__ __forceinline__ void mma_tile(float (&acc)[2][4][4],
    const bf16* sAh, const bf16* sAl, int SA, int arow, int ka0,
    const bf16* sBh, const bf16* sBl, int SB, int bcol, int kb0, int lane)
{
    uint32_t ah[2][4], al[2][4];
    {
        int r = arow + (lane & 15);
        int c = ka0 + ((lane >> 4) << 3);
        ldsm4(ah[0], sptr(sAh + r * SA + c));
        ldsm4(ah[1], sptr(sAh + (r + 16) * SA + c));
        ldsm4(al[0], sptr(sAl + r * SA + c));
        ldsm4(al[1], sptr(sAl + (r + 16) * SA + c));
    }
    uint32_t bh[4][2], bl[4][2];
    int m = lane >> 3, rr = lane & 7;
#pragma unroll
    for (int g = 0; g < 2; g++) {
        uint32_t t[4];
        if (!TRANSB) {
            int n  = bcol + g * 16 + ((m >> 1) << 3) + rr;
            int kk = kb0 + ((m & 1) << 3);
            ldsm4(t, sptr(sBh + n * SB + kk));
            bh[2*g][0]=t[0]; bh[2*g][1]=t[1]; bh[2*g+1][0]=t[2]; bh[2*g+1][1]=t[3];
            ldsm4(t, sptr(sBl + n * SB + kk));
            bl[2*g][0]=t[0]; bl[2*g][1]=t[1]; bl[2*g+1][0]=t[2]; bl[2*g+1][1]=t[3];
        } else {
            int kr = kb0 + ((m & 1) << 3) + rr;
            int nc = bcol + g * 16 + ((m >> 1) << 3);
            ldsm4t(t, sptr(sBh + kr * SB + nc));
            bh[2*g][0]=t[0]; bh[2*g][1]=t[1]; bh[2*g+1][0]=t[2]; bh[2*g+1][1]=t[3];
            ldsm4t(t, sptr(sBl + kr * SB + nc));
            bl[2*g][0]=t[0]; bl[2*g][1]=t[1]; bl[2*g+1][0]=t[2]; bl[2*g+1][1]=t[3];
        }
    }
#pragma unroll
    for (int mi = 0; mi < 2; mi++)
#pragma unroll
        for (int ni = 0; ni < 4; ni++) {
            mma_bf(acc[mi][ni], ah[mi], bh[ni]);
            mma_bf(acc[mi][ni], ah[mi], bl[ni]);
            mma_bf(acc[mi][ni], al[mi], bh[ni]);
        }
}

__device__ __forceinline__ void stage2a(bf16* dh, bf16* dl, int stride,
    const bf16* gh, const bf16* gl, int ld, int rows, int c8, int tid)
{
    for (int i = tid; i < rows * c8; i += 256) {
        int r = i / c8, c = (i - r * c8) * 8;
        cpa16(dh + r * stride + c, gh + (size_t)r * ld + c);
        cpa16(dl + r * stride + c, gl + (size_t)r * ld + c);
    }
}
__device__ __forceinline__ void stage128(bf16* dh, bf16* dl, int stride,
    const bf16* gh, const bf16* gl, int ld, int rows, int c8, int tid)
{
    for (int i = tid; i < rows * c8; i += 128) {
        int r = i / c8, c = (i - r * c8) * 8;
        cpa16(dh + r * stride + c, gh + (size_t)r * ld + c);
        cpa16(dl + r * stride + c, gl + (size_t)r * ld + c);
    }
}

__global__ __launch_bounds__(256)
void split_all(const float* __restrict__ x, const float* __restrict__ qw,
               const float* __restrict__ kw, const float* __restrict__ vw,
               const float* __restrict__ ow, const float* __restrict__ w2) {
    int b = blockIdx.x;
    const float* src; bf16 *hi, *lo; int base;
    if (b < 4096)       { src = x;  hi = g_xh;  lo = g_xl;  base = b; }
    else if (b < 8192)  { src = qw; hi = g_qwh; lo = g_qwl; base = b - 4096; }
    else if (b < 12288) { src = kw; hi = g_kwh; lo = g_kwl; base = b - 8192; }
    else if (b < 16384) { src = vw; hi = g_vwh; lo = g_vwl; base = b - 12288; }
    else if (b < 24576) { src = ow; hi = g_owh; lo = g_owl; base = b - 16384; }
    else                { src = w2; hi = g_w2h; lo = g_w2l; base = b - 24576; }
    int i = base * 256 + threadIdx.x;
    float v = src[i];
    bf16 h = __float2bfloat16(v);
    hi[i] = h;
    lo[i] = __float2bfloat16(v - __bfloat162float(h));
}

// ---- fused x@w1^T (split wlow) and beta = 2*sigmoid(x@btw^T + b) ----
__global__ __launch_bounds__(256)
void lowrank(const float* __restrict__ x, const float* __restrict__ w1,
             const float* __restrict__ btw, const float* __restrict__ btb) {
    __shared__ float sx[1024];
    __shared__ float red[64][5];
    int t = blockIdx.x, tid = threadIdx.x;
    *(float4*)&sx[tid*4] = *(const float4*)&x[(size_t)t*1024 + tid*4];
    __syncthreads();
    int c = tid & 63, s = tid >> 6;
    const float* w = (c < 32) ? (w1 + (size_t)c*1024) : (btw + (size_t)(c-32)*1024);
    float acc = 0.f;
    for (int k = s*256; k < s*256 + 256; k += 4) {
        float4 wv = *(const float4*)&w[k];
        acc += wv.x*sx[k] + wv.y*sx[k+1] + wv.z*sx[k+2] + wv.w*sx[k+3];
    }
    red[c][s] = acc;
    __syncthreads();
    if (tid < 64) {
        float v = red[tid][0] + red[tid][1] + red[tid][2] + red[tid][3];
        if (tid < 32) {
            bf16 hh = __float2bfloat16(v);
            g_wlh[t*32 + tid] = hh;
            g_wll[t*32 + tid] = __float2bfloat16(v - __bfloat162float(hh));
        } else {
            int hr = tid - 32;
            g_betah[hr*TT + t] = 2.f / (1.f + __expf(-(v + btb[hr])));
        }
    }
}

// ---- wraw = wlow @ w2^T on tensor cores, K=32 single chunk ----
__global__ __launch_bounds__(256)
void tc_wraw() {
    __shared__ __align__(16) bf16 sA[15360];  // Ah 0 | Al 5120 | Bh 10240 | Bl 12800
    int tid = threadIdx.x, lane = tid & 31, w = tid >> 5;
    int m0 = blockIdx.y * 128, n0 = blockIdx.x * 64;
    int arow = (w >> 1) * 32, bcol = (w & 1) * 32;
    float acc[2][4][4] = {};
    stage2a(sA, sA+5120, 40, g_wlh + (size_t)m0*32, g_wll + (size_t)m0*32, 32, 128, 4, tid);
    stage2a(sA+10240, sA+12800, 40, g_w2h + (size_t)n0*32, g_w2l + (size_t)n0*32, 32, 64, 4, tid);
    CPC(); CPW(0);
    __syncthreads();
    mma_tile<false>(acc, sA, sA+5120, 40, arow, 0,  sA+10240, sA+12800, 40, bcol, 0,  lane);
    mma_tile<false>(acc, sA, sA+5120, 40, arow, 16, sA+10240, sA+12800, 40, bcol, 16, lane);
    int r0 = arow + (lane >> 2), c0 = bcol + (lane & 3) * 2;
#pragma unroll
    for (int mi = 0; mi < 2; mi++)
#pragma unroll
        for (int ni = 0; ni < 4; ni++)
#pragma unroll
            for (int hf = 0; hf < 2; hf++) {
                int row = m0 + r0 + mi*16 + hf*8;
                int col = n0 + c0 + ni*8;
                *(float2*)&g_wraw[(size_t)row * 4096 + col] =
                    make_float2(acc[mi][ni][hf*2], acc[mi][ni][hf*2+1]);
            }
}

// ---- dense C = A@B^T, tile 128x64, 2-buffer pipeline (out-projection) ----
__global__ __launch_bounds__(256)
void tc_dense(const bf16* __restrict__ Ah, const bf16* __restrict__ Al, int lda,
              const bf16* __restrict__ Bh, const bf16* __restrict__ Bl, int ldb,
              int K, float* __restrict__ Cf, int ldc)
{
    extern __shared__ __align__(16) bf16 sm[];
    const int BUF = 15360;
    int tid = threadIdx.x, lane = tid & 31, w = tid >> 5;
    int m0 = blockIdx.y * 128, n0 = blockIdx.x * 64;
    int arow = (w >> 1) * 32, bcol = (w & 1) * 32;
    float acc[2][4][4] = {};
    int nk = K / 32;
    auto stg = [&](int b, int k0) {
        bf16* p = sm + b * BUF;
        stage2a(p, p+5120, 40, Ah + (size_t)m0*lda + k0, Al + (size_t)m0*lda + k0, lda, 128, 4, tid);
        stage2a(p+10240, p+12800, 40, Bh + (size_t)n0*ldb + k0, Bl + (size_t)n0*ldb + k0, ldb, 64, 4, tid);
        CPC();
    };
    stg(0, 0);
    for (int i = 0; i < nk; i++) {
        if (i+1 < nk) { stg((i+1)&1, (i+1)*32); CPW(1); } else CPW(0);
        __syncthreads();
        bf16* p = sm + (i&1)*BUF;
        mma_tile<false>(acc, p, p+5120, 40, arow, 0,  p+10240, p+12800, 40, bcol, 0,  lane);
        mma_tile<false>(acc, p, p+5120, 40, arow, 16, p+10240, p+12800, 40, bcol, 16, lane);
        __syncthreads();
    }
    int r0 = arow + (lane >> 2), c0 = bcol + (lane & 3) * 2;
#pragma unroll
    for (int mi = 0; mi < 2; mi++)
#pragma unroll
        for (int ni = 0; ni < 4; ni++)
#pragma unroll
            for (int hf = 0; hf < 2; hf++) {
                int row = m0 + r0 + mi*16 + hf*8;
                int col = n0 + c0 + ni*8;
                *(float2*)&Cf[(size_t)row * ldc + col] =
                    make_float2(acc[mi][ni][hf*2], acc[mi][ni][hf*2+1]);
            }
}

// ---- fused q/k/v projections (k also written negated) ----
__global__ __launch_bounds__(256)
void tc_qkv()
{
    extern __shared__ __align__(16) bf16 sm[];
    const int BUF = 15360;
    const bf16 *Bh, *Bl; bf16 *Ch, *Cl;
    if (blockIdx.z == 0)      { Bh = g_qwh; Bl = g_qwl; Ch = g_qh; Cl = g_ql; }
    else if (blockIdx.z == 1) { Bh = g_kwh; Bl = g_kwl; Ch = g_kh; Cl = g_kl; }
    else                      { Bh = g_vwh; Bl = g_vwl; Ch = g_vh; Cl = g_vl; }
    int tid = threadIdx.x, lane = tid & 31, w = tid >> 5;
    int m0 = blockIdx.y * 128, n0 = blockIdx.x * 64;
    int arow = (w >> 1) * 32, bcol = (w & 1) * 32;
    float acc[2][4][4] = {};
    auto stg = [&](int b, int k0) {
        bf16* p = sm + b * BUF;
        stage2a(p, p+5120, 40, g_xh + (size_t)m0*1024 + k0, g_xl + (size_t)m0*1024 + k0, 1024, 128, 4, tid);
        stage2a(p+10240, p+12800, 40, Bh + (size_t)n0*1024 + k0, Bl + (size_t)n0*1024 + k0, 1024, 64, 4, tid);
        CPC();
    };
    stg(0, 0);
    for (int i = 0; i < 32; i++) {
        if (i+1 < 32) { stg((i+1)&1, (i+1)*32); CPW(1); } else CPW(0);
        __syncthreads();
        bf16* p = sm + (i&1)*BUF;
        mma_tile<false>(acc, p, p+5120, 40, arow, 0,  p+10240, p+12800, 40, bcol, 0,  lane);
        mma_tile<false>(acc, p, p+5120, 40, arow, 16, p+10240, p+12800, 40, bcol, 16, lane);
        __syncthreads();
    }
    int r0 = arow + (lane >> 2), c0 = bcol + (lane & 3) * 2;
#pragma unroll
    for (int mi = 0; mi < 2; mi++)
#pragma unroll
        for (int ni = 0; ni < 4; ni++)
#pragma unroll
            for (int hf = 0; hf < 2; hf++) {
                int row = m0 + r0 + mi*16 + hf*8;
                int col = n0 + c0 + ni*8;
                float v0 = acc[mi][ni][hf*2], v1 = acc[mi][ni][hf*2+1];
                st_split2(Ch, Cl, (size_t)row * 1024 + col, v0, v1);
                if (blockIdx.z == 1)
                    st_split2(g_knh, g_knl, (size_t)row * 1024 + col, -v0, -v1);
            }
}

// ---- fused per-head GEMMs: z encodes stage (Mw / rhs / QW), K=64 ----
__global__ __launch_bounds__(256)
void tc_headz()
{
    int jt = blockIdx.x, it = blockIdx.y, z = blockIdx.z;
    if (jt > 2 * it + 1) return;
    int stage, h;
    if (z < 32)      { stage = 0; h = z; }
    else if (z < 64) { stage = 1; h = z - 32; }
    else             { stage = 2; h = z - 64; }

    const bf16 *Ahp, *Alp, *Bhp, *Blp;
    int lda, ldb, mode;
    const float* rowscale = nullptr;
    if (stage == 0) {
        Ahp = g_wdh + (size_t)h*65536; Alp = g_wdl + (size_t)h*65536; lda = 64;
        Bhp = g_wdh + (size_t)h*65536; Blp = g_wdl + (size_t)h*65536; ldb = 64;
        mode = 1; rowscale = g_betah;
    } else if (stage == 1) {
        Ahp = g_wdh + (size_t)h*65536; Alp = g_wdl + (size_t)h*65536; lda = 64;
        Bhp = g_kh + (size_t)(h>>1)*64; Blp = g_kl + (size_t)(h>>1)*64; ldb = 1024;
        mode = 1; rowscale = g_betah;
    } else {
        Ahp = g_qh + (size_t)(h>>1)*64; Alp = g_ql + (size_t)(h>>1)*64; lda = 1024;
        Bhp = g_wdh + (size_t)h*65536; Blp = g_wdl + (size_t)h*65536; ldb = 64;
        mode = 2;
    }
    Ahp += (size_t)(it*128) * lda; Alp += (size_t)(it*128) * lda;
    Bhp += (size_t)(jt*64)  * ldb; Blp += (size_t)(jt*64)  * ldb;

    extern __shared__ __align__(16) bf16 sm[];
    const int BUF = 15360;
    int tid = threadIdx.x, lane = tid & 31, w = tid >> 5;
    int arow = (w >> 1) * 32, bcol = (w & 1) * 32;
    float acc[2][4][4] = {};
    auto stg = [&](int b, int k0) {
        bf16* p = sm + b * BUF;
        stage2a(p, p+5120, 40, Ahp + k0, Alp + k0, lda, 128, 4, tid);
        stage2a(p+10240, p+12800, 40, Bhp + k0, Blp + k0, ldb, 64, 4, tid);
        CPC();
    };
    stg(0, 0);
#pragma unroll
    for (int i = 0; i < 2; i++) {
        if (i == 0) { stg(1, 32); CPW(1); } else CPW(0);
        __syncthreads();
        bf16* p = sm + i*BUF;
        mma_tile<false>(acc, p, p+5120, 40, arow, 0,  p+10240, p+12800, 40, bcol, 0,  lane);
        mma_tile<false>(acc, p, p+5120, 40, arow, 16, p+10240, p+12800, 40, bcol, 16, lane);
        __syncthreads();
    }
    int r0 = arow + (lane >> 2), c0 = bcol + (lane & 3) * 2;
    size_t hb = (size_t)h * HS;
#pragma unroll
    for (int mi = 0; mi < 2; mi++)
#pragma unroll
        for (int ni = 0; ni < 4; ni++)
#pragma unroll
            for (int hf = 0; hf < 2; hf++) {
                int row = it*128 + r0 + mi*16 + hf*8;
                int col = jt*64 + c0 + ni*8;
                float v0 = acc[mi][ni][hf*2], v1 = acc[mi][ni][hf*2+1];
                float sc = rowscale ? rowscale[h * TT + row] : 1.f;
                v0 *= sc; v1 *= sc;
                if (mode == 1) { if (col   >= row) v0 = 0.f;
                                 if (col+1 >= row) v1 = 0.f; }
                else           { if (col   >  row) v0 = 0.f;
                                 if (col+1 >  row) v1 = 0.f; }
                size_t off = hb + (size_t)row * TT + col;
                if (stage == 0)      st_split2(g_Mwh, g_Mwl, off, v0, v1);
                else if (stage == 1) *(float2*)&g_rhs[off] = make_float2(v0, v1);
                else                 st_split2(g_QWh, g_QWl, off, v0, v1);
            }
}

__global__ __launch_bounds__(64)
void compute_tinv() {
    __shared__ float L[64][65];
    __shared__ float X[64][65];
    int ch = blockIdx.x, h = blockIdx.y, c = threadIdx.x;
    size_t base = (size_t)h * HS + (size_t)(ch*64) * TT + ch*64;
    for (int r = 0; r < 64; r++) {
        L[r][c] = __bfloat162float(g_Mwh[base + (size_t)r*TT + c]) +
                  __bfloat162float(g_Mwl[base + (size_t)r*TT + c]);
        X[r][c] = (r == c) ? 1.f : 0.f;
    }
    __syncthreads();
    for (int r = 1; r < 64; r++) {
        if (c < r) {
            float acc = 0.f;
            for (int s = c; s < r; s++) acc += L[r][s] * X[s][c];
            X[r][c] = -acc;
        }
        __syncthreads();
    }
    size_t ob = ((size_t)(h*16 + ch)) * 4096;
    for (int r = 0; r < 64; r++) {
        float v = X[r][c];
        bf16 hh = __float2bfloat16(v);
        g_Tvh[ob + r*64 + c] = hh;
        g_Tvl[ob + r*64 + c] = __float2bfloat16(v - __bfloat162float(hh));
    }
}

// ---- blocked forward substitution, ALL chunks in one launch ----
__global__ __launch_bounds__(256)
void tc_solve_all() {
    extern __shared__ __align__(16) bf16 sm[];
    const int BUF = 13824;
    int jb = blockIdx.x, h = blockIdx.y;
    int tid = threadIdx.x, lane = tid & 31, w = tid >> 5;
    int arow = (w >> 2) * 32, bcol = (w & 3) * 32;
    size_t hb = (size_t)h * HS;
    int r0 = arow + (lane >> 2), c0 = bcol + (lane & 3) * 2;

    for (int ci = 2*jb; ci < 16; ci++) {
        float acc[2][4][4];
#pragma unroll
        for (int mi = 0; mi < 2; mi++)
#pragma unroll
            for (int ni = 0; ni < 4; ni++)
#pragma unroll
                for (int hf = 0; hf < 2; hf++) {
                    float2 v = *(const float2*)&g_rhs[hb +
                        (size_t)(ci*64 + r0 + mi*16 + hf*8) * TT + jb*128 + c0 + ni*8];
                    acc[mi][ni][hf*2]   = -v.x;
                    acc[mi][ni][hf*2+1] = -v.y;
                }
        int nch = 2 * (ci - 2*jb);
        auto stg = [&](int b, int m) {
            int s = 2*jb + (m >> 1), kc = (m & 1) * 32;
            bf16* p = sm + b * BUF;
            stage2a(p, p+2560, 40,
                    g_Mwh + hb + (size_t)(ci*64)*TT + s*64 + kc,
                    g_Mwl + hb + (size_t)(ci*64)*TT + s*64 + kc, TT, 64, 4, tid);
            stage2a(p+5120, p+9472, 136,
                    g_Bh + hb + (size_t)(s*64 + kc)*TT + jb*128,
                    g_Bl + hb + (size_t)(s*64 + kc)*TT + jb*128, TT, 32, 16, tid);
            CPC();
        };
        if (nch > 0) stg(0, 0);
        for (int m = 0; m < nch; m++) {
            if (m+1 < nch) { stg((m+1)&1, m+1); CPW(1); } else CPW(0);
            __syncthreads();
            bf16* p = sm + (m&1)*BUF;
            mma_tile<true>(acc, p, p+2560, 40, arow, 0,  p+5120, p+9472, 136, bcol, 0,  lane);
            mma_tile<true>(acc, p, p+2560, 40, arow, 16, p+5120, p+9472, 136, bcol, 16, lane);
            __syncthreads();
        }
        bf16 *sPh = sm, *sPl = sm + 8704, *sTh = sm + 17408, *sTl = sm + 19968;
        __syncthreads();
#pragma unroll
        for (int mi = 0; mi < 2; mi++)
#pragma unroll
            for (int ni = 0; ni < 4; ni++)
#pragma unroll
                for (int hf = 0; hf < 2; hf++) {
                    int r = r0 + mi*16 + hf*8, c = c0 + ni*8;
                    st_split2(sPh, sPl, (size_t)r*136 + c,
                              -acc[mi][ni][hf*2], -acc[mi][ni][hf*2+1]);
                }
#pragma unroll
        for (int mi = 0; mi < 2; mi++)
#pragma unroll
            for (int ni = 0; ni < 4; ni++)
#pragma unroll
                for (int e = 0; e < 4; e++) acc[mi][ni][e] = 0.f;
        size_t tb = ((size_t)(h*16 + ci)) * 4096;
#pragma unroll
        for (int kc = 0; kc < 64; kc += 32) {
            stage2a(sTh, sTl, 40, g_Tvh + tb + kc, g_Tvl + tb + kc, 64, 64, 4, tid);
            CPC(); CPW(0);
            __syncthreads();
            mma_tile<true>(acc, sTh, sTl, 40, arow, 0,  sPh, sPl, 136, bcol, kc,      lane);
            mma_tile<true>(acc, sTh, sTl, 40, arow, 16, sPh, sPl, 136, bcol, kc + 16, lane);
            __syncthreads();
        }
#pragma unroll
        for (int mi = 0; mi < 2; mi++)
#pragma unroll
            for (int ni = 0; ni < 4; ni++)
#pragma unroll
                for (int hf = 0; hf < 2; hf++) {
                    int row = ci*64 + r0 + mi*16 + hf*8;
                    int col = jb*128 + c0 + ni*8;
                    st_split2(g_Bh, g_Bl, hb + (size_t)row*TT + col,
                              acc[mi][ni][hf*2], acc[mi][ni][hf*2+1]);
                }
        __syncthreads();
    }
}

// ==== flash-fused attention with inline QK: logits + online softmax + PV ====
// acc = QW·Bmat + q·(−k)  →  logits = −acc·scale
// Buffers: BUF=10240 elts: Ah 0 (2560) | Al 2560 | Bh 5120 | Bl 7424 (stride 72, QW path)
//                                                | Bl 7680 (stride 40, qk path)
__global__ __launch_bounds__(128)
void tc_attn() {
    extern __shared__ __align__(16) bf16 sm[];
    const int BUF = 10240;
    bf16* sPh = sm + 20480;
    bf16* sPl = sm + 25088;
    float* sMrow = (float*)(sm + 29696);
    float* sSrow = sMrow + 64;
    float* sPmax = sSrow + 64;      // [64][2]
    float* sPsum = sPmax + 128;     // [64][2]
    int it = 15 - blockIdx.x, p = blockIdx.y, h = blockIdx.z;
    int tid = threadIdx.x, lane = tid & 31, w = tid >> 5;
    int arow = (w >> 1) * 32, bcol = (w & 1) * 32;
    int rl0 = arow + (lane >> 2), cl0 = bcol + (lane & 3) * 2;
    size_t hb = (size_t)h * HS;
    size_t qoff = (size_t)(h >> 1) * 64;
    for (int i = tid; i < 64; i += 128) { sMrow[i] = -1e30f; sSrow[i] = 0.f; }
    float o[2][4][4];
#pragma unroll
    for (int mi = 0; mi < 2; mi++)
#pragma unroll
        for (int ni = 0; ni < 4; ni++)
#pragma unroll
            for (int e = 0; e < 4; e++) o[mi][ni][e] = 0.f;
    __syncthreads();

    for (int jt = p; jt <= it; jt += 2) {
        float acc[2][4][4] = {};
        int nch = 2 * (it - jt + 1);
        auto stg = [&](int b, int m) {
            int kb = jt + (m >> 1), kc = (m & 1) * 32;
            bf16* pp = sm + b * BUF;
            stage128(pp, pp+2560, 40,
                g_QWh + hb + (size_t)(it*64)*TT + kb*64 + kc,
                g_QWl + hb + (size_t)(it*64)*TT + kb*64 + kc, TT, 64, 4, tid);
            stage128(pp+5120, pp+7424, 72,
                g_Bh + hb + (size_t)(kb*64 + kc)*TT + jt*64,
                g_Bl + hb + (size_t)(kb*64 + kc)*TT + jt*64, TT, 32, 8, tid);
            CPC();
        };
        stg(0, 0);
        for (int m = 0; m < nch; m++) {
            if (m+1 < nch) { stg((m+1)&1, m+1); CPW(1); } else CPW(0);
            __syncthreads();
            bf16* pp = sm + (m&1)*BUF;
            mma_tile<true>(acc, pp, pp+2560, 40, arow, 0,  pp+5120, pp+7424, 72, bcol, 0,  lane);
            mma_tile<true>(acc, pp, pp+2560, 40, arow, 16, pp+5120, pp+7424, 72, bcol, 16, lane);
            __syncthreads();
        }
        // qk chunks: A = q rows (it), B = -k rows (jt), K=64 as 2x32
#pragma unroll
        for (int s = 0; s < 2; s++) {
            bf16* pp = sm + s * BUF;
            stage128(pp, pp+2560, 40,
                g_qh + qoff + (size_t)(it*64)*1024 + s*32,
                g_ql + qoff + (size_t)(it*64)*1024 + s*32, 1024, 64, 4, tid);
            stage128(pp+5120, pp+7680, 40,
                g_knh + qoff + (size_t)(jt*64)*1024 + s*32,
                g_knl + qoff + (size_t)(jt*64)*1024 + s*32, 1024, 64, 4, tid);
            CPC();
        }
        CPW(0);
        __syncthreads();
#pragma unroll
        for (int s = 0; s < 2; s++) {
            bf16* pp = sm + s * BUF;
            mma_tile<false>(acc, pp, pp+2560, 40, arow, 0,  pp+5120, pp+7680, 40, bcol, 0,  lane);
            mma_tile<false>(acc, pp, pp+2560, 40, arow, 16, pp+5120, pp+7680, 40, bcol, 16, lane);
        }
        __syncthreads();
        // logits = -acc*scale, mask, per-row tile max
        float pmv[2][2];
#pragma unroll
        for (int mi = 0; mi < 2; mi++)
#pragma unroll
            for (int hf = 0; hf < 2; hf++) {
                int rl = rl0 + mi*16 + hf*8;
                int row_g = it*64 + rl;
                float best = -1e30f;
#pragma unroll
                for (int ni = 0; ni < 4; ni++) {
                    int col_g = jt*64 + cl0 + ni*8;
                    float L0 = -acc[mi][ni][hf*2]   * ATT_SCALE;
                    float L1 = -acc[mi][ni][hf*2+1] * ATT_SCALE;
                    if (jt == it) {
                        if (col_g     > row_g) L0 = -1e30f;
                        if (col_g + 1 > row_g) L1 = -1e30f;
                    }
                    acc[mi][ni][hf*2]   = L0;
                    acc[mi][ni][hf*2+1] = L1;
                    best = fmaxf(best, fmaxf(L0, L1));
                }
                pmv[mi][hf] = best;
            }
#pragma unroll
        for (int mi = 0; mi < 2; mi++)
#pragma unroll
            for (int hf = 0; hf < 2; hf++) {
                float v = pmv[mi][hf];
                v = fmaxf(v, __shfl_xor_sync(~0u, v, 1));
                v = fmaxf(v, __shfl_xor_sync(~0u, v, 2));
                pmv[mi][hf] = v;
            }
        if ((lane & 3) == 0)
#pragma unroll
            for (int mi = 0; mi < 2; mi++)
#pragma unroll
                for (int hf = 0; hf < 2; hf++)
                    sPmax[(rl0 + mi*16 + hf*8)*2 + (w & 1)] = pmv[mi][hf];
        __syncthreads();
        // exp + P store + rescale O
        float psv[2][2];
#pragma unroll
        for (int mi = 0; mi < 2; mi++)
#pragma unroll
            for (int hf = 0; hf < 2; hf++) {
                int rl = rl0 + mi*16 + hf*8;
                float mo = sMrow[rl];
                float m2 = fmaxf(mo, fmaxf(sPmax[rl*2], sPmax[rl*2+1]));
                float f = __expf(mo - m2);
                float sum = 0.f;
#pragma unroll
                for (int ni = 0; ni < 4; ni++) {
                    float e0 = __expf(acc[mi][ni][hf*2]   - m2);
                    float e1 = __expf(acc[mi][ni][hf*2+1] - m2);
                    acc[mi][ni][hf*2] = e0; acc[mi][ni][hf*2+1] = e1;
                    sum += e0 + e1;
                    o[mi][ni][hf*2]   *= f;
                    o[mi][ni][hf*2+1] *= f;
                    st_split2(sPh, sPl, (size_t)rl*72 + cl0 + ni*8, e0, e1);
                }
                psv[mi][hf] = sum;
            }
#pragma unroll
        for (int mi = 0; mi < 2; mi++)
#pragma unroll
            for (int hf = 0; hf < 2; hf++) {
                float v = psv[mi][hf];
                v += __shfl_xor_sync(~0u, v, 1);
                v += __shfl_xor_sync(~0u, v, 2);
                psv[mi][hf] = v;
            }
        if ((lane & 3) == 0)
#pragma unroll
            for (int mi = 0; mi < 2; mi++)
#pragma unroll
                for (int hf = 0; hf < 2; hf++)
                    sPsum[(rl0 + mi*16 + hf*8)*2 + (w & 1)] = psv[mi][hf];
        // stage V tile into buffer 0
        stage128(sm, sm + 4608, 72,
                 g_vh + (size_t)(jt*64)*1024 + qoff,
                 g_vl + (size_t)(jt*64)*1024 + qoff, 1024, 64, 8, tid);
        CPC();
        __syncthreads();
        if (tid < 64) {
            float mo = sMrow[tid];
            float m2 = fmaxf(mo, fmaxf(sPmax[tid*2], sPmax[tid*2+1]));
            float f = __expf(mo - m2);
            sSrow[tid] = sSrow[tid] * f + sPsum[tid*2] + sPsum[tid*2+1];
            sMrow[tid] = m2;
        }
        CPW(0);
        __syncthreads();
        // PV
#pragma unroll
        for (int mi = 0; mi < 2; mi++)
#pragma unroll
            for (int ni = 0; ni < 4; ni++)
#pragma unroll
                for (int e = 0; e < 4; e++) acc[mi][ni][e] = 0.f;
        mma_tile<true>(acc, sPh, sPl, 72, arow, 0,  sm, sm+4608, 72, bcol, 0,  lane);
        mma_tile<true>(acc, sPh, sPl, 72, arow, 16, sm, sm+4608, 72, bcol, 16, lane);
        mma_tile<true>(acc, sPh, sPl, 72, arow, 32, sm, sm+4608, 72, bcol, 32, lane);
        mma_tile<true>(acc, sPh, sPl, 72, arow, 48, sm, sm+4608, 72, bcol, 48, lane);
#pragma unroll
        for (int mi = 0; mi < 2; mi++)
#pragma unroll
            for (int ni = 0; ni < 4; ni++)
#pragma unroll
                for (int e = 0; e < 4; e++) o[mi][ni][e] += acc[mi][ni][e];
        __syncthreads();
    }
    float* PB = g_rhs + ((size_t)((h*16 + it)*2 + p)) * 4224;
#pragma unroll
    for (int mi = 0; mi < 2; mi++)
#pragma unroll
        for (int ni = 0; ni < 4; ni++)
#pragma unroll
            for (int hf = 0; hf < 2; hf++) {
                int rl = rl0 + mi*16 + hf*8;
                *(float2*)&PB[rl*64 + cl0 + ni*8] =
                    make_float2(o[mi][ni][hf*2], o[mi][ni][hf*2+1]);
            }
    if (tid < 64) { PB[4096 + tid] = sMrow[tid]; PB[4160 + tid] = sSrow[tid]; }
}

__global__ __launch_bounds__(128)
void attn_merge() {
    int it = blockIdx.x, h = blockIdx.y, tid = threadIdx.x;
    const float* P0 = g_rhs + ((size_t)((h*16 + it)*2)) * 4224;
    const float* P1 = P0 + 4224;
    __shared__ float w0[64], w1[64], inv[64];
    if (tid < 64) {
        float m0 = P0[4096+tid], m1 = P1[4096+tid];
        float mm = fmaxf(m0, m1);
        float e0 = __expf(m0 - mm), e1 = __expf(m1 - mm);
        float s = P0[4160+tid]*e0 + P1[4160+tid]*e1;
        w0[tid] = e0; w1[tid] = e1; inv[tid] = 1.f / s;
    }
    __syncthreads();
    for (int i = tid; i < 4096; i += 128) {
        int r = i >> 6, c = i & 63;
        float v = (P0[i]*w0[r] + P1[i]*w1[r]) * inv[r];
        size_t off = (size_t)(it*64 + r) * 2048 + h*64 + c;
        bf16 hh = __float2bfloat16(v);
        g_O2h[off] = hh;
        g_O2l[off] = __float2bfloat16(v - __bfloat162float(hh));
    }
}

__global__ __launch_bounds__(64)
void wdir_kernel(const float* __restrict__ wraw, const float* __restrict__ conv_w,
                 const float* __restrict__ omega, const float* __restrict__ phi) {
    int t = blockIdx.x, hr = blockIdx.y, d = threadIdx.x;
    int hkv = hr >> 1, r = hr & 1;
    int cA = hkv * 256 + (2*r) * 64 + d;
    int cB = cA + 64;
    float a = 0.f, b = 0.f;
#pragma unroll
    for (int i = 0; i < 3; i++) {
        int tt = t + i - 2;
        if (tt >= 0) {
            a += wraw[(size_t)tt * 4096 + cA] * conv_w[cA*3 + i];
            b += wraw[(size_t)tt * 4096 + cB] * conv_w[cB*3 + i];
        }
    }
    a = a / (1.f + expf(-a));
    b = b / (1.f + expf(-b));
    float th = omega[r] * (float)t + phi[r];
    float w = a * cosf(th) + b * sinf(th);
    float ss = w * w;
#pragma unroll
    for (int o = 16; o; o >>= 1) ss += __shfl_xor_sync(~0u, ss, o);
    __shared__ float sh[2];
    if ((d & 31) == 0) sh[d >> 5] = ss;
    __syncthreads();
    float tot = sh[0] + sh[1];
    float val = w * rsqrtf(tot + 1e-6f);
    size_t off = ((size_t)hr * TT + t) * 64 + d;
    bf16 hh = __float2bfloat16(val);
    g_wdh[off] = hh;
    g_wdl[off] = __float2bfloat16(val - __bfloat162float(hh));
}

#define GS(p, s) cudaGetSymbolAddress((void**)&p, s)

extern "C" void kernel_launch(void* const* d_in, const int* in_sizes, int n_in,
                              void* d_out, int out_size) {
    const float* x    = (const float*)d_in[0];
    const float* q_w  = (const float*)d_in[1];
    const float* k_w  = (const float*)d_in[2];
    const float* v_w  = (const float*)d_in[3];
    const float* w1   = (const float*)d_in[4];
    const float* w2   = (const float*)d_in[5];
    const float* cw   = (const float*)d_in[6];
    const float* btw  = (const float*)d_in[7];
    const float* btb  = (const float*)d_in[8];
    const float* ow   = (const float*)d_in[9];
    const float* omega= (const float*)d_in[10];
    const float* phi  = (const float*)d_in[11];
    float* out = (float*)d_out;

    float* pwraw;
    bf16 *pO2h,*pO2l,*powh,*powl;
    GS(pwraw,g_wraw);
    GS(pO2h,g_O2h); GS(pO2l,g_O2l); GS(powh,g_owh); GS(powl,g_owl);

    static bool attr_done = false;
    if (!attr_done) {
        cudaFuncSetAttribute(tc_dense,     cudaFuncAttributeMaxDynamicSharedMemorySize, 61440);
        cudaFuncSetAttribute(tc_qkv,       cudaFuncAttributeMaxDynamicSharedMemorySize, 61440);
        cudaFuncSetAttribute(tc_headz,     cudaFuncAttributeMaxDynamicSharedMemorySize, 61440);
        cudaFuncSetAttribute(tc_solve_all, cudaFuncAttributeMaxDynamicSharedMemorySize, 55296);
        cudaFuncSetAttribute(tc_attn,      cudaFuncAttributeMaxDynamicSharedMemorySize, 60928);
        attr_done = true;
    }

    split_all<<<25088, 256>>>(x, q_w, k_w, v_w, ow, w2);

    lowrank<<<1024, 256>>>(x, w1, btw, btb);
    tc_wraw<<<dim3(64,8), 256>>>();
    wdir_kernel<<<dim3(1024, 32), 64>>>(pwraw, cw, omega, phi);

    tc_qkv<<<dim3(16,8,3), 256, 61440>>>();
    tc_headz<<<dim3(16,8,96), 256, 61440>>>();

    compute_tinv<<<dim3(16,32), 64>>>();
    tc_solve_all<<<dim3(8,32), 256, 55296>>>();

    tc_attn<<<dim3(16,2,32), 128, 60928>>>();
    attn_merge<<<dim3(16,32), 128>>>();

    tc_dense<<<dim3(16,8), 256, 61440>>>(pO2h, pO2l, 2048, powh, powl, 2048, 2048,
                                         out, 1024);
}

// round 14
// speedup vs baseline: 1.0170x; 1.0170x over previous
#include <cuda_runtime.h>
#include <cuda_bf16.h>
#include <cstdint>

using bf16 = __nv_bfloat16;
#define TT 1024
#define HS 1048576
#define ATT_SCALE 0.125f

__device__ float g_wraw[TT*4096];
__device__ float g_betah[32*TT];
__device__ float g_rhs[32*HS];      // solve rhs, later attn split-K scratch
__device__ float g_QK [16*HS];

__device__ bf16 g_xh[1048576],  g_xl[1048576];
__device__ bf16 g_qwh[1048576], g_qwl[1048576];
__device__ bf16 g_kwh[1048576], g_kwl[1048576];
__device__ bf16 g_vwh[1048576], g_vwl[1048576];
__device__ bf16 g_owh[2097152], g_owl[2097152];
__device__ bf16 g_w2h[131072],  g_w2l[131072];
__device__ bf16 g_wlh[32768],   g_wll[32768];
__device__ bf16 g_qh[1048576],  g_ql[1048576];
__device__ bf16 g_kh[1048576],  g_kl[1048576];
__device__ bf16 g_vh[1048576],  g_vl[1048576];
__device__ bf16 g_wdh[2097152], g_wdl[2097152];
__device__ bf16 g_Mwh[33554432], g_Mwl[33554432];
__device__ bf16 g_Bh [33554432], g_Bl [33554432];
__device__ bf16 g_QWh[33554432], g_QWl[33554432];
__device__ bf16 g_Tvh[2097152],  g_Tvl[2097152];
__device__ bf16 g_O2h[2097152],  g_O2l[2097152];

__device__ __forceinline__ uint32_t sptr(const void* p) {
    return (uint32_t)__cvta_generic_to_shared(p);
}
__device__ __forceinline__ void ldsm4(uint32_t* r, uint32_t a) {
    asm volatile("ldmatrix.sync.aligned.m8n8.x4.shared.b16 {%0,%1,%2,%3}, [%4];"
        : "=r"(r[0]), "=r"(r[1]), "=r"(r[2]), "=r"(r[3]) : "r"(a));
}
__device__ __forceinline__ void ldsm4t(uint32_t* r, uint32_t a) {
    asm volatile("ldmatrix.sync.aligned.m8n8.x4.trans.shared.b16 {%0,%1,%2,%3}, [%4];"
        : "=r"(r[0]), "=r"(r[1]), "=r"(r[2]), "=r"(r[3]) : "r"(a));
}
__device__ __forceinline__ void mma_bf(float* c, const uint32_t* a, const uint32_t* b) {
    asm volatile(
        "mma.sync.aligned.m16n8k16.row.col.f32.bf16.bf16.f32 "
        "{%0,%1,%2,%3},{%4,%5,%6,%7},{%8,%9},{%0,%1,%2,%3};"
        : "+f"(c[0]), "+f"(c[1]), "+f"(c[2]), "+f"(c[3])
        : "r"(a[0]), "r"(a[1]), "r"(a[2]), "r"(a[3]), "r"(b[0]), "r"(b[1]));
}
__device__ __forceinline__ void st_split2(bf16* hi, bf16* lo, size_t off, float v0, float v1) {
    bf16 h0 = __float2bfloat16(v0), h1 = __float2bfloat16(v1);
    *(__nv_bfloat162*)(hi + off) = __halves2bfloat162(h0, h1);
    *(__nv_bfloat162*)(lo + off) = __halves2bfloat162(
        __float2bfloat16(v0 - __bfloat162float(h0)),
        __float2bfloat16(v1 - __bfloat162float(h1)));
}
__device__ __forceinline__ void cpa16(void* s, const void* g) {
    asm volatile("cp.async.cg.shared.global [%0], [%1], 16;" :: "r"(sptr(s)), "l"(g) : "memory");
}
#define CPC() asm volatile("cp.async.commit_group;" ::: "memory")
#define CPW(n) asm volatile("cp.async.wait_group %0;" :: "n"(n) : "memory")

template<bool TRANSB>
__device__ __forceinline__ void mma_tile(float (&acc)[2][4][4],
    const bf16* sAh, const bf16* sAl, int SA, int arow, int ka0,
    const bf16* sBh, const bf16* sBl, int SB, int bcol, int kb0, int lane)
{
    uint32_t ah[2][4], al[2][4];
    {
        int r = arow + (lane & 15);
        int c = ka0 + ((lane >> 4) << 3);
        ldsm4(ah[0], sptr(sAh + r * SA + c));
        ldsm4(ah[1], sptr(sAh + (r + 16) * SA + c));
        ldsm4(al[0], sptr(sAl + r * SA + c));
        ldsm4(al[1], sptr(sAl + (r + 16) * SA + c));
    }
    uint32_t bh[4][2], bl[4][2];
    int m = lane >> 3, rr = lane & 7;
#pragma unroll
    for (int g = 0; g < 2; g++) {
        uint32_t t[4];
        if (!TRANSB) {
            int n  = bcol + g * 16 + ((m >> 1) << 3) + rr;
            int kk = kb0 + ((m & 1) << 3);
            ldsm4(t, sptr(sBh + n * SB + kk));
            bh[2*g][0]=t[0]; bh[2*g][1]=t[1]; bh[2*g+1][0]=t[2]; bh[2*g+1][1]=t[3];
            ldsm4(t, sptr(sBl + n * SB + kk));
            bl[2*g][0]=t[0]; bl[2*g][1]=t[1]; bl[2*g+1][0]=t[2]; bl[2*g+1][1]=t[3];
        } else {
            int kr = kb0 + ((m & 1) << 3) + rr;
            int nc = bcol + g * 16 + ((m >> 1) << 3);
            ldsm4t(t, sptr(sBh + kr * SB + nc));
            bh[2*g][0]=t[0]; bh[2*g][1]=t[1]; bh[2*g+1][0]=t[2]; bh[2*g+1][1]=t[3];
            ldsm4t(t, sptr(sBl + kr * SB + nc));
            bl[2*g][0]=t[0]; bl[2*g][1]=t[1]; bl[2*g+1][0]=t[2]; bl[2*g+1][1]=t[3];
        }
    }
#pragma unroll
    for (int mi = 0; mi < 2; mi++)
#pragma unroll
        for (int ni = 0; ni < 4; ni++) {
            mma_bf(acc[mi][ni], ah[mi], bh[ni]);
            mma_bf(acc[mi][ni], ah[mi], bl[ni]);
            mma_bf(acc[mi][ni], al[mi], bh[ni]);
        }
}

__device__ __forceinline__ void stage2a(bf16* dh, bf16* dl, int stride,
    const bf16* gh, const bf16* gl, int ld, int rows, int c8, int tid)
{
    for (int i = tid; i < rows * c8; i += 256) {
        int r = i / c8, c = (i - r * c8) * 8;
        cpa16(dh + r * stride + c, gh + (size_t)r * ld + c);
        cpa16(dl + r * stride + c, gl + (size_t)r * ld + c);
    }
}
__device__ __forceinline__ void stage128(bf16* dh, bf16* dl, int stride,
    const bf16* gh, const bf16* gl, int ld, int rows, int c8, int tid)
{
    for (int i = tid; i < rows * c8; i += 128) {
        int r = i / c8, c = (i - r * c8) * 8;
        cpa16(dh + r * stride + c, gh + (size_t)r * ld + c);
        cpa16(dl + r * stride + c, gl + (size_t)r * ld + c);
    }
}

__global__ __launch_bounds__(256)
void split_all(const float* __restrict__ x, const float* __restrict__ qw,
               const float* __restrict__ kw, const float* __restrict__ vw,
               const float* __restrict__ ow, const float* __restrict__ w2) {
    int b = blockIdx.x;
    const float* src; bf16 *hi, *lo; int base;
    if (b < 4096)       { src = x;  hi = g_xh;  lo = g_xl;  base = b; }
    else if (b < 8192)  { src = qw; hi = g_qwh; lo = g_qwl; base = b - 4096; }
    else if (b < 12288) { src = kw; hi = g_kwh; lo = g_kwl; base = b - 8192; }
    else if (b < 16384) { src = vw; hi = g_vwh; lo = g_vwl; base = b - 12288; }
    else if (b < 24576) { src = ow; hi = g_owh; lo = g_owl; base = b - 16384; }
    else                { src = w2; hi = g_w2h; lo = g_w2l; base = b - 24576; }
    int i = base * 256 + threadIdx.x;
    float v = src[i];
    bf16 h = __float2bfloat16(v);
    hi[i] = h;
    lo[i] = __float2bfloat16(v - __bfloat162float(h));
}

// ---- fused x@w1^T (split wlow) and beta = 2*sigmoid(x@btw^T + b) ----
__global__ __launch_bounds__(256)
void lowrank(const float* __restrict__ x, const float* __restrict__ w1,
             const float* __restrict__ btw, const float* __restrict__ btb) {
    __shared__ float sx[1024];
    __shared__ float red[64][5];
    int t = blockIdx.x, tid = threadIdx.x;
    *(float4*)&sx[tid*4] = *(const float4*)&x[(size_t)t*1024 + tid*4];
    __syncthreads();
    int c = tid & 63, s = tid >> 6;
    const float* w = (c < 32) ? (w1 + (size_t)c*1024) : (btw + (size_t)(c-32)*1024);
    float acc = 0.f;
    for (int k = s*256; k < s*256 + 256; k += 4) {
        float4 wv = *(const float4*)&w[k];
        acc += wv.x*sx[k] + wv.y*sx[k+1] + wv.z*sx[k+2] + wv.w*sx[k+3];
    }
    red[c][s] = acc;
    __syncthreads();
    if (tid < 64) {
        float v = red[tid][0] + red[tid][1] + red[tid][2] + red[tid][3];
        if (tid < 32) {
            bf16 hh = __float2bfloat16(v);
            g_wlh[t*32 + tid] = hh;
            g_wll[t*32 + tid] = __float2bfloat16(v - __bfloat162float(hh));
        } else {
            int hr = tid - 32;
            g_betah[hr*TT + t] = 2.f / (1.f + __expf(-(v + btb[hr])));
        }
    }
}

// ---- wraw = wlow @ w2^T on tensor cores, K=32 single chunk ----
__global__ __launch_bounds__(256)
void tc_wraw() {
    __shared__ __align__(16) bf16 sA[15360];
    int tid = threadIdx.x, lane = tid & 31, w = tid >> 5;
    int m0 = blockIdx.y * 128, n0 = blockIdx.x * 64;
    int arow = (w >> 1) * 32, bcol = (w & 1) * 32;
    float acc[2][4][4] = {};
    stage2a(sA, sA+5120, 40, g_wlh + (size_t)m0*32, g_wll + (size_t)m0*32, 32, 128, 4, tid);
    stage2a(sA+10240, sA+12800, 40, g_w2h + (size_t)n0*32, g_w2l + (size_t)n0*32, 32, 64, 4, tid);
    CPC(); CPW(0);
    __syncthreads();
    mma_tile<false>(acc, sA, sA+5120, 40, arow, 0,  sA+10240, sA+12800, 40, bcol, 0,  lane);
    mma_tile<false>(acc, sA, sA+5120, 40, arow, 16, sA+10240, sA+12800, 40, bcol, 16, lane);
    int r0 = arow + (lane >> 2), c0 = bcol + (lane & 3) * 2;
#pragma unroll
    for (int mi = 0; mi < 2; mi++)
#pragma unroll
        for (int ni = 0; ni < 4; ni++)
#pragma unroll
            for (int hf = 0; hf < 2; hf++) {
                int row = m0 + r0 + mi*16 + hf*8;
                int col = n0 + c0 + ni*8;
                *(float2*)&g_wraw[(size_t)row * 4096 + col] =
                    make_float2(acc[mi][ni][hf*2], acc[mi][ni][hf*2+1]);
            }
}

// ---- dense C = A@B^T, tile 128x64, 2-buffer pipeline (out-projection) ----
__global__ __launch_bounds__(256)
void tc_dense(const bf16* __restrict__ Ah, const bf16* __restrict__ Al, int lda,
              const bf16* __restrict__ Bh, const bf16* __restrict__ Bl, int ldb,
              int K, float* __restrict__ Cf, int ldc)
{
    extern __shared__ __align__(16) bf16 sm[];
    const int BUF = 15360;
    int tid = threadIdx.x, lane = tid & 31, w = tid >> 5;
    int m0 = blockIdx.y * 128, n0 = blockIdx.x * 64;
    int arow = (w >> 1) * 32, bcol = (w & 1) * 32;
    float acc[2][4][4] = {};
    int nk = K / 32;
    auto stg = [&](int b, int k0) {
        bf16* p = sm + b * BUF;
        stage2a(p, p+5120, 40, Ah + (size_t)m0*lda + k0, Al + (size_t)m0*lda + k0, lda, 128, 4, tid);
        stage2a(p+10240, p+12800, 40, Bh + (size_t)n0*ldb + k0, Bl + (size_t)n0*ldb + k0, ldb, 64, 4, tid);
        CPC();
    };
    stg(0, 0);
    for (int i = 0; i < nk; i++) {
        if (i+1 < nk) { stg((i+1)&1, (i+1)*32); CPW(1); } else CPW(0);
        __syncthreads();
        bf16* p = sm + (i&1)*BUF;
        mma_tile<false>(acc, p, p+5120, 40, arow, 0,  p+10240, p+12800, 40, bcol, 0,  lane);
        mma_tile<false>(acc, p, p+5120, 40, arow, 16, p+10240, p+12800, 40, bcol, 16, lane);
        __syncthreads();
    }
    int r0 = arow + (lane >> 2), c0 = bcol + (lane & 3) * 2;
#pragma unroll
    for (int mi = 0; mi < 2; mi++)
#pragma unroll
        for (int ni = 0; ni < 4; ni++)
#pragma unroll
            for (int hf = 0; hf < 2; hf++) {
                int row = m0 + r0 + mi*16 + hf*8;
                int col = n0 + c0 + ni*8;
                *(float2*)&Cf[(size_t)row * ldc + col] =
                    make_float2(acc[mi][ni][hf*2], acc[mi][ni][hf*2+1]);
            }
}

// ---- fused q/k/v projections ----
__global__ __launch_bounds__(256)
void tc_qkv()
{
    extern __shared__ __align__(16) bf16 sm[];
    const int BUF = 15360;
    const bf16 *Bh, *Bl; bf16 *Ch, *Cl;
    if (blockIdx.z == 0)      { Bh = g_qwh; Bl = g_qwl; Ch = g_qh; Cl = g_ql; }
    else if (blockIdx.z == 1) { Bh = g_kwh; Bl = g_kwl; Ch = g_kh; Cl = g_kl; }
    else                      { Bh = g_vwh; Bl = g_vwl; Ch = g_vh; Cl = g_vl; }
    int tid = threadIdx.x, lane = tid & 31, w = tid >> 5;
    int m0 = blockIdx.y * 128, n0 = blockIdx.x * 64;
    int arow = (w >> 1) * 32, bcol = (w & 1) * 32;
    float acc[2][4][4] = {};
    auto stg = [&](int b, int k0) {
        bf16* p = sm + b * BUF;
        stage2a(p, p+5120, 40, g_xh + (size_t)m0*1024 + k0, g_xl + (size_t)m0*1024 + k0, 1024, 128, 4, tid);
        stage2a(p+10240, p+12800, 40, Bh + (size_t)n0*1024 + k0, Bl + (size_t)n0*1024 + k0, 1024, 64, 4, tid);
        CPC();
    };
    stg(0, 0);
    for (int i = 0; i < 32; i++) {
        if (i+1 < 32) { stg((i+1)&1, (i+1)*32); CPW(1); } else CPW(0);
        __syncthreads();
        bf16* p = sm + (i&1)*BUF;
        mma_tile<false>(acc, p, p+5120, 40, arow, 0,  p+10240, p+12800, 40, bcol, 0,  lane);
        mma_tile<false>(acc, p, p+5120, 40, arow, 16, p+10240, p+12800, 40, bcol, 16, lane);
        __syncthreads();
    }
    int r0 = arow + (lane >> 2), c0 = bcol + (lane & 3) * 2;
#pragma unroll
    for (int mi = 0; mi < 2; mi++)
#pragma unroll
        for (int ni = 0; ni < 4; ni++)
#pragma unroll
            for (int hf = 0; hf < 2; hf++) {
                int row = m0 + r0 + mi*16 + hf*8;
                int col = n0 + c0 + ni*8;
                st_split2(Ch, Cl, (size_t)row * 1024 + col,
                          acc[mi][ni][hf*2], acc[mi][ni][hf*2+1]);
            }
}

// ---- fused per-head GEMMs: z encodes stage (Mw / rhs / QK / QW), K=64 ----
__global__ __launch_bounds__(256)
void tc_headz()
{
    int jt = blockIdx.x, it = blockIdx.y, z = blockIdx.z;
    if (jt > 2 * it + 1) return;
    int stage, h;
    if (z < 32)      { stage = 0; h = z; }
    else if (z < 64) { stage = 1; h = z - 32; }
    else if (z < 80) { stage = 2; h = z - 64; }
    else             { stage = 3; h = z - 80; }

    const bf16 *Ahp, *Alp, *Bhp, *Blp;
    int lda, ldb, mode;
    const float* rowscale = nullptr;
    if (stage == 0) {
        Ahp = g_wdh + (size_t)h*65536; Alp = g_wdl + (size_t)h*65536; lda = 64;
        Bhp = g_wdh + (size_t)h*65536; Blp = g_wdl + (size_t)h*65536; ldb = 64;
        mode = 1; rowscale = g_betah;
    } else if (stage == 1) {
        Ahp = g_wdh + (size_t)h*65536; Alp = g_wdl + (size_t)h*65536; lda = 64;
        Bhp = g_kh + (size_t)(h>>1)*64; Blp = g_kl + (size_t)(h>>1)*64; ldb = 1024;
        mode = 1; rowscale = g_betah;
    } else if (stage == 2) {
        Ahp = g_qh + (size_t)h*64; Alp = g_ql + (size_t)h*64; lda = 1024;
        Bhp = g_kh + (size_t)h*64; Blp = g_kl + (size_t)h*64; ldb = 1024;
        mode = 2;
    } else {
        Ahp = g_qh + (size_t)(h>>1)*64; Alp = g_ql + (size_t)(h>>1)*64; lda = 1024;
        Bhp = g_wdh + (size_t)h*65536; Blp = g_wdl + (size_t)h*65536; ldb = 64;
        mode = 2;
    }
    Ahp += (size_t)(it*128) * lda; Alp += (size_t)(it*128) * lda;
    Bhp += (size_t)(jt*64)  * ldb; Blp += (size_t)(jt*64)  * ldb;

    extern __shared__ __align__(16) bf16 sm[];
    const int BUF = 15360;
    int tid = threadIdx.x, lane = tid & 31, w = tid >> 5;
    int arow = (w >> 1) * 32, bcol = (w & 1) * 32;
    float acc[2][4][4] = {};
    auto stg = [&](int b, int k0) {
        bf16* p = sm + b * BUF;
        stage2a(p, p+5120, 40, Ahp + k0, Alp + k0, lda, 128, 4, tid);
        stage2a(p+10240, p+12800, 40, Bhp + k0, Blp + k0, ldb, 64, 4, tid);
        CPC();
    };
    stg(0, 0);
#pragma unroll
    for (int i = 0; i < 2; i++) {
        if (i == 0) { stg(1, 32); CPW(1); } else CPW(0);
        __syncthreads();
        bf16* p = sm + i*BUF;
        mma_tile<false>(acc, p, p+5120, 40, arow, 0,  p+10240, p+12800, 40, bcol, 0,  lane);
        mma_tile<false>(acc, p, p+5120, 40, arow, 16, p+10240, p+12800, 40, bcol, 16, lane);
        __syncthreads();
    }
    int r0 = arow + (lane >> 2), c0 = bcol + (lane & 3) * 2;
    size_t hb = (size_t)h * HS;
#pragma unroll
    for (int mi = 0; mi < 2; mi++)
#pragma unroll
        for (int ni = 0; ni < 4; ni++)
#pragma unroll
            for (int hf = 0; hf < 2; hf++) {
                int row = it*128 + r0 + mi*16 + hf*8;
                int col = jt*64 + c0 + ni*8;
                float v0 = acc[mi][ni][hf*2], v1 = acc[mi][ni][hf*2+1];
                float sc = rowscale ? rowscale[h * TT + row] : 1.f;
                v0 *= sc; v1 *= sc;
                if (mode == 1) { if (col   >= row) v0 = 0.f;
                                 if (col+1 >= row) v1 = 0.f; }
                else           { if (col   >  row) v0 = 0.f;
                                 if (col+1 >  row) v1 = 0.f; }
                size_t off = hb + (size_t)row * TT + col;
                if (stage == 0)      st_split2(g_Mwh, g_Mwl, off, v0, v1);
                else if (stage == 1) *(float2*)&g_rhs[off] = make_float2(v0, v1);
                else if (stage == 2) *(float2*)&g_QK[off]  = make_float2(v0, v1);
                else                 st_split2(g_QWh, g_QWl, off, v0, v1);
            }
}

__global__ __launch_bounds__(64)
void compute_tinv() {
    __shared__ float L[64][65];
    __shared__ float X[64][65];
    int ch = blockIdx.x, h = blockIdx.y, c = threadIdx.x;
    size_t base = (size_t)h * HS + (size_t)(ch*64) * TT + ch*64;
    for (int r = 0; r < 64; r++) {
        L[r][c] = __bfloat162float(g_Mwh[base + (size_t)r*TT + c]) +
                  __bfloat162float(g_Mwl[base + (size_t)r*TT + c]);
        X[r][c] = (r == c) ? 1.f : 0.f;
    }
    __syncthreads();
    for (int r = 1; r < 64; r++) {
        if (c < r) {
            float acc = 0.f;
            for (int s = c; s < r; s++) acc += L[r][s] * X[s][c];
            X[r][c] = -acc;
        }
        __syncthreads();
    }
    size_t ob = ((size_t)(h*16 + ch)) * 4096;
    for (int r = 0; r < 64; r++) {
        float v = X[r][c];
        bf16 hh = __float2bfloat16(v);
        g_Tvh[ob + r*64 + c] = hh;
        g_Tvl[ob + r*64 + c] = __float2bfloat16(v - __bfloat162float(hh));
    }
}

// ---- blocked forward substitution, ALL chunks in one launch ----
__global__ __launch_bounds__(256)
void tc_solve_all() {
    extern __shared__ __align__(16) bf16 sm[];
    const int BUF = 13824;
    int jb = blockIdx.x, h = blockIdx.y;
    int tid = threadIdx.x, lane = tid & 31, w = tid >> 5;
    int arow = (w >> 2) * 32, bcol = (w & 3) * 32;
    size_t hb = (size_t)h * HS;
    int r0 = arow + (lane >> 2), c0 = bcol + (lane & 3) * 2;

    for (int ci = 2*jb; ci < 16; ci++) {
        float acc[2][4][4];
#pragma unroll
        for (int mi = 0; mi < 2; mi++)
#pragma unroll
            for (int ni = 0; ni < 4; ni++)
#pragma unroll
                for (int hf = 0; hf < 2; hf++) {
                    float2 v = *(const float2*)&g_rhs[hb +
                        (size_t)(ci*64 + r0 + mi*16 + hf*8) * TT + jb*128 + c0 + ni*8];
                    acc[mi][ni][hf*2]   = -v.x;
                    acc[mi][ni][hf*2+1] = -v.y;
                }
        int nch = 2 * (ci - 2*jb);
        auto stg = [&](int b, int m) {
            int s = 2*jb + (m >> 1), kc = (m & 1) * 32;
            bf16* p = sm + b * BUF;
            stage2a(p, p+2560, 40,
                    g_Mwh + hb + (size_t)(ci*64)*TT + s*64 + kc,
                    g_Mwl + hb + (size_t)(ci*64)*TT + s*64 + kc, TT, 64, 4, tid);
            stage2a(p+5120, p+9472, 136,
                    g_Bh + hb + (size_t)(s*64 + kc)*TT + jb*128,
                    g_Bl + hb + (size_t)(s*64 + kc)*TT + jb*128, TT, 32, 16, tid);
            CPC();
        };
        if (nch > 0) stg(0, 0);
        for (int m = 0; m < nch; m++) {
            if (m+1 < nch) { stg((m+1)&1, m+1); CPW(1); } else CPW(0);
            __syncthreads();
            bf16* p = sm + (m&1)*BUF;
            mma_tile<true>(acc, p, p+2560, 40, arow, 0,  p+5120, p+9472, 136, bcol, 0,  lane);
            mma_tile<true>(acc, p, p+2560, 40, arow, 16, p+5120, p+9472, 136, bcol, 16, lane);
            __syncthreads();
        }
        bf16 *sPh = sm, *sPl = sm + 8704, *sTh = sm + 17408, *sTl = sm + 19968;
        __syncthreads();
#pragma unroll
        for (int mi = 0; mi < 2; mi++)
#pragma unroll
            for (int ni = 0; ni < 4; ni++)
#pragma unroll
                for (int hf = 0; hf < 2; hf++) {
                    int r = r0 + mi*16 + hf*8, c = c0 + ni*8;
                    st_split2(sPh, sPl, (size_t)r*136 + c,
                              -acc[mi][ni][hf*2], -acc[mi][ni][hf*2+1]);
                }
#pragma unroll
        for (int mi = 0; mi < 2; mi++)
#pragma unroll
            for (int ni = 0; ni < 4; ni++)
#pragma unroll
                for (int e = 0; e < 4; e++) acc[mi][ni][e] = 0.f;
        size_t tb = ((size_t)(h*16 + ci)) * 4096;
#pragma unroll
        for (int kc = 0; kc < 64; kc += 32) {
            stage2a(sTh, sTl, 40, g_Tvh + tb + kc, g_Tvl + tb + kc, 64, 64, 4, tid);
            CPC(); CPW(0);
            __syncthreads();
            mma_tile<true>(acc, sTh, sTl, 40, arow, 0,  sPh, sPl, 136, bcol, kc,      lane);
            mma_tile<true>(acc, sTh, sTl, 40, arow, 16, sPh, sPl, 136, bcol, kc + 16, lane);
            __syncthreads();
        }
#pragma unroll
        for (int mi = 0; mi < 2; mi++)
#pragma unroll
            for (int ni = 0; ni < 4; ni++)
#pragma unroll
                for (int hf = 0; hf < 2; hf++) {
                    int row = ci*64 + r0 + mi*16 + hf*8;
                    int col = jb*128 + c0 + ni*8;
                    st_split2(g_Bh, g_Bl, hb + (size_t)row*TT + col,
                              acc[mi][ni][hf*2], acc[mi][ni][hf*2+1]);
                }
        __syncthreads();
    }
}

// ==== flash-fused attention: logits + online softmax + PV, split-K over jt ====
__global__ __launch_bounds__(128)
void tc_attn() {
    extern __shared__ __align__(16) bf16 sm[];
    const int BUF = 9728;           // A 64x40 h+l (5120) | B 32x72 h+l (4608)
    bf16* sPh = sm + 19456;
    bf16* sPl = sm + 24064;
    float* sMrow = (float*)(sm + 28672);
    float* sSrow = sMrow + 64;
    float* sPmax = sSrow + 64;      // [64][2]
    float* sPsum = sPmax + 128;     // [64][2]
    int it = 15 - blockIdx.x, p = blockIdx.y, h = blockIdx.z;
    int tid = threadIdx.x, lane = tid & 31, w = tid >> 5;
    int arow = (w >> 1) * 32, bcol = (w & 1) * 32;
    int rl0 = arow + (lane >> 2), cl0 = bcol + (lane & 3) * 2;
    size_t hb = (size_t)h * HS;
    size_t qb = (size_t)(h >> 1) * HS;
    for (int i = tid; i < 64; i += 128) { sMrow[i] = -1e30f; sSrow[i] = 0.f; }
    float o[2][4][4];
#pragma unroll
    for (int mi = 0; mi < 2; mi++)
#pragma unroll
        for (int ni = 0; ni < 4; ni++)
#pragma unroll
            for (int e = 0; e < 4; e++) o[mi][ni][e] = 0.f;
    __syncthreads();

    for (int jt = p; jt <= it; jt += 2) {
        float acc[2][4][4] = {};
        int nch = 2 * (it - jt + 1);
        auto stg = [&](int b, int m) {
            int kb = jt + (m >> 1), kc = (m & 1) * 32;
            bf16* pp = sm + b * BUF;
            stage128(pp, pp+2560, 40,
                g_QWh + hb + (size_t)(it*64)*TT + kb*64 + kc,
                g_QWl + hb + (size_t)(it*64)*TT + kb*64 + kc, TT, 64, 4, tid);
            stage128(pp+5120, pp+7424, 72,
                g_Bh + hb + (size_t)(kb*64 + kc)*TT + jt*64,
                g_Bl + hb + (size_t)(kb*64 + kc)*TT + jt*64, TT, 32, 8, tid);
            CPC();
        };
        stg(0, 0);
        for (int m = 0; m < nch; m++) {
            if (m+1 < nch) { stg((m+1)&1, m+1); CPW(1); } else CPW(0);
            __syncthreads();
            bf16* pp = sm + (m&1)*BUF;
            mma_tile<true>(acc, pp, pp+2560, 40, arow, 0,  pp+5120, pp+7424, 72, bcol, 0,  lane);
            mma_tile<true>(acc, pp, pp+2560, 40, arow, 16, pp+5120, pp+7424, 72, bcol, 16, lane);
            __syncthreads();
        }
        // logits (qk - acc)*scale, mask, per-row tile max
        float pmv[2][2];
#pragma unroll
        for (int mi = 0; mi < 2; mi++)
#pragma unroll
            for (int hf = 0; hf < 2; hf++) {
                int rl = rl0 + mi*16 + hf*8;
                int row_g = it*64 + rl;
                float best = -1e30f;
#pragma unroll
                for (int ni = 0; ni < 4; ni++) {
                    int col_g = jt*64 + cl0 + ni*8;
                    float2 q = *(const float2*)&g_QK[qb + (size_t)row_g*TT + col_g];
                    float L0 = (q.x - acc[mi][ni][hf*2])   * ATT_SCALE;
                    float L1 = (q.y - acc[mi][ni][hf*2+1]) * ATT_SCALE;
                    if (jt == it) {
                        if (col_g     > row_g) L0 = -1e30f;
                        if (col_g + 1 > row_g) L1 = -1e30f;
                    }
                    acc[mi][ni][hf*2]   = L0;
                    acc[mi][ni][hf*2+1] = L1;
                    best = fmaxf(best, fmaxf(L0, L1));
                }
                pmv[mi][hf] = best;
            }
#pragma unroll
        for (int mi = 0; mi < 2; mi++)
#pragma unroll
            for (int hf = 0; hf < 2; hf++) {
                float v = pmv[mi][hf];
                v = fmaxf(v, __shfl_xor_sync(~0u, v, 1));
                v = fmaxf(v, __shfl_xor_sync(~0u, v, 2));
                pmv[mi][hf] = v;
            }
        if ((lane & 3) == 0)
#pragma unroll
            for (int mi = 0; mi < 2; mi++)
#pragma unroll
                for (int hf = 0; hf < 2; hf++)
                    sPmax[(rl0 + mi*16 + hf*8)*2 + (w & 1)] = pmv[mi][hf];
        __syncthreads();
        // exp + P store + rescale O + V staging
        float psv[2][2];
#pragma unroll
        for (int mi = 0; mi < 2; mi++)
#pragma unroll
            for (int hf = 0; hf < 2; hf++) {
                int rl = rl0 + mi*16 + hf*8;
                float mo = sMrow[rl];
                float m2 = fmaxf(mo, fmaxf(sPmax[rl*2], sPmax[rl*2+1]));
                float f = __expf(mo - m2);
                float sum = 0.f;
#pragma unroll
                for (int ni = 0; ni < 4; ni++) {
                    float e0 = __expf(acc[mi][ni][hf*2]   - m2);
                    float e1 = __expf(acc[mi][ni][hf*2+1] - m2);
                    acc[mi][ni][hf*2] = e0; acc[mi][ni][hf*2+1] = e1;
                    sum += e0 + e1;
                    o[mi][ni][hf*2]   *= f;
                    o[mi][ni][hf*2+1] *= f;
                    st_split2(sPh, sPl, (size_t)rl*72 + cl0 + ni*8, e0, e1);
                }
                psv[mi][hf] = sum;
            }
#pragma unroll
        for (int mi = 0; mi < 2; mi++)
#pragma unroll
            for (int hf = 0; hf < 2; hf++) {
                float v = psv[mi][hf];
                v += __shfl_xor_sync(~0u, v, 1);
                v += __shfl_xor_sync(~0u, v, 2);
                psv[mi][hf] = v;
            }
        if ((lane & 3) == 0)
#pragma unroll
            for (int mi = 0; mi < 2; mi++)
#pragma unroll
                for (int hf = 0; hf < 2; hf++)
                    sPsum[(rl0 + mi*16 + hf*8)*2 + (w & 1)] = psv[mi][hf];
        stage128(sm, sm + 4608, 72,
                 g_vh + (size_t)(jt*64)*1024 + (size_t)(h>>1)*64,
                 g_vl + (size_t)(jt*64)*1024 + (size_t)(h>>1)*64, 1024, 64, 8, tid);
        CPC();
        __syncthreads();
        if (tid < 64) {
            float mo = sMrow[tid];
            float m2 = fmaxf(mo, fmaxf(sPmax[tid*2], sPmax[tid*2+1]));
            float f = __expf(mo - m2);
            sSrow[tid] = sSrow[tid] * f + sPsum[tid*2] + sPsum[tid*2+1];
            sMrow[tid] = m2;
        }
        CPW(0);
        __syncthreads();
#pragma unroll
        for (int mi = 0; mi < 2; mi++)
#pragma unroll
            for (int ni = 0; ni < 4; ni++)
#pragma unroll
                for (int e = 0; e < 4; e++) acc[mi][ni][e] = 0.f;
        mma_tile<true>(acc, sPh, sPl, 72, arow, 0,  sm, sm+4608, 72, bcol, 0,  lane);
        mma_tile<true>(acc, sPh, sPl, 72, arow, 16, sm, sm+4608, 72, bcol, 16, lane);
        mma_tile<true>(acc, sPh, sPl, 72, arow, 32, sm, sm+4608, 72, bcol, 32, lane);
        mma_tile<true>(acc, sPh, sPl, 72, arow, 48, sm, sm+4608, 72, bcol, 48, lane);
#pragma unroll
        for (int mi = 0; mi < 2; mi++)
#pragma unroll
            for (int ni = 0; ni < 4; ni++)
#pragma unroll
                for (int e = 0; e < 4; e++) o[mi][ni][e] += acc[mi][ni][e];
        __syncthreads();
    }
    float* PB = g_rhs + ((size_t)((h*16 + it)*2 + p)) * 4224;
#pragma unroll
    for (int mi = 0; mi < 2; mi++)
#pragma unroll
        for (int ni = 0; ni < 4; ni++)
#pragma unroll
            for (int hf = 0; hf < 2; hf++) {
                int rl = rl0 + mi*16 + hf*8;
                *(float2*)&PB[rl*64 + cl0 + ni*8] =
                    make_float2(o[mi][ni][hf*2], o[mi][ni][hf*2+1]);
            }
    if (tid < 64) { PB[4096 + tid] = sMrow[tid]; PB[4160 + tid] = sSrow[tid]; }
}

__global__ __launch_bounds__(128)
void attn_merge() {
    int it = blockIdx.x, h = blockIdx.y, tid = threadIdx.x;
    const float* P0 = g_rhs + ((size_t)((h*16 + it)*2)) * 4224;
    const float* P1 = P0 + 4224;
    __shared__ float w0[64], w1[64], inv[64];
    if (tid < 64) {
        float m0 = P0[4096+tid], m1 = P1[4096+tid];
        float mm = fmaxf(m0, m1);
        float e0 = __expf(m0 - mm), e1 = __expf(m1 - mm);
        float s = P0[4160+tid]*e0 + P1[4160+tid]*e1;
        w0[tid] = e0; w1[tid] = e1; inv[tid] = 1.f / s;
    }
    __syncthreads();
    for (int i = tid; i < 4096; i += 128) {
        int r = i >> 6, c = i & 63;
        float v = (P0[i]*w0[r] + P1[i]*w1[r]) * inv[r];
        size_t off = (size_t)(it*64 + r) * 2048 + h*64 + c;
        bf16 hh = __float2bfloat16(v);
        g_O2h[off] = hh;
        g_O2l[off] = __float2bfloat16(v - __bfloat162float(hh));
    }
}

__global__ __launch_bounds__(64)
void wdir_kernel(const float* __restrict__ wraw, const float* __restrict__ conv_w,
                 const float* __restrict__ omega, const float* __restrict__ phi) {
    int t = blockIdx.x, hr = blockIdx.y, d = threadIdx.x;
    int hkv = hr >> 1, r = hr & 1;
    int cA = hkv * 256 + (2*r) * 64 + d;
    int cB = cA + 64;
    float a = 0.f, b = 0.f;
#pragma unroll
    for (int i = 0; i < 3; i++) {
        int tt = t + i - 2;
        if (tt >= 0) {
            a += wraw[(size_t)tt * 4096 + cA] * conv_w[cA*3 + i];
            b += wraw[(size_t)tt * 4096 + cB] * conv_w[cB*3 + i];
        }
    }
    a = a / (1.f + expf(-a));
    b = b / (1.f + expf(-b));
    float th = omega[r] * (float)t + phi[r];
    float w = a * cosf(th) + b * sinf(th);
    float ss = w * w;
#pragma unroll
    for (int o = 16; o; o >>= 1) ss += __shfl_xor_sync(~0u, ss, o);
    __shared__ float sh[2];
    if ((d & 31) == 0) sh[d >> 5] = ss;
    __syncthreads();
    float tot = sh[0] + sh[1];
    float val = w * rsqrtf(tot + 1e-6f);
    size_t off = ((size_t)hr * TT + t) * 64 + d;
    bf16 hh = __float2bfloat16(val);
    g_wdh[off] = hh;
    g_wdl[off] = __float2bfloat16(val - __bfloat162float(hh));
}

#define GS(p, s) cudaGetSymbolAddress((void**)&p, s)

extern "C" void kernel_launch(void* const* d_in, const int* in_sizes, int n_in,
                              void* d_out, int out_size) {
    const float* x    = (const float*)d_in[0];
    const float* q_w  = (const float*)d_in[1];
    const float* k_w  = (const float*)d_in[2];
    const float* v_w  = (const float*)d_in[3];
    const float* w1   = (const float*)d_in[4];
    const float* w2   = (const float*)d_in[5];
    const float* cw   = (const float*)d_in[6];
    const float* btw  = (const float*)d_in[7];
    const float* btb  = (const float*)d_in[8];
    const float* ow   = (const float*)d_in[9];
    const float* omega= (const float*)d_in[10];
    const float* phi  = (const float*)d_in[11];
    float* out = (float*)d_out;

    float* pwraw;
    bf16 *pO2h,*pO2l,*powh,*powl;
    GS(pwraw,g_wraw);
    GS(pO2h,g_O2h); GS(pO2l,g_O2l); GS(powh,g_owh); GS(powl,g_owl);

    static bool attr_done = false;
    if (!attr_done) {
        cudaFuncSetAttribute(tc_dense,     cudaFuncAttributeMaxDynamicSharedMemorySize, 61440);
        cudaFuncSetAttribute(tc_qkv,       cudaFuncAttributeMaxDynamicSharedMemorySize, 61440);
        cudaFuncSetAttribute(tc_headz,     cudaFuncAttributeMaxDynamicSharedMemorySize, 61440);
        cudaFuncSetAttribute(tc_solve_all, cudaFuncAttributeMaxDynamicSharedMemorySize, 55296);
        cudaFuncSetAttribute(tc_attn,      cudaFuncAttributeMaxDynamicSharedMemorySize, 58880);
        attr_done = true;
    }

    split_all<<<25088, 256>>>(x, q_w, k_w, v_w, ow, w2);

    lowrank<<<1024, 256>>>(x, w1, btw, btb);
    tc_wraw<<<dim3(64,8), 256>>>();
    wdir_kernel<<<dim3(1024, 32), 64>>>(pwraw, cw, omega, phi);

    tc_qkv<<<dim3(16,8,3), 256, 61440>>>();
    tc_headz<<<dim3(16,8,112), 256, 61440>>>();

    compute_tinv<<<dim3(16,32), 64>>>();
    tc_solve_all<<<dim3(8,32), 256, 55296>>>();

    tc_attn<<<dim3(16,2,32), 128, 58880>>>();
    attn_merge<<<dim3(16,32), 128>>>();

    tc_dense<<<dim3(16,8), 256, 61440>>>(pO2h, pO2l, 2048, powh, powl, 2048, 2048,
                                         out, 1024);
}

// round 15
// speedup vs baseline: 1.0936x; 1.0753x over previous
#include <cuda_runtime.h>
#include <cuda_bf16.h>
#include <cstdint>

using bf16 = __nv_bfloat16;
#define TT 1024
#define HS 1048576
#define ATT_SCALE 0.125f

__device__ float g_wraw[TT*4096];
__device__ float g_betah[32*TT];
__device__ float g_rhs[32*HS];
__device__ float g_QK [16*HS];

__device__ bf16 g_xh[1048576],  g_xl[1048576];
__device__ bf16 g_qwh[1048576], g_qwl[1048576];
__device__ bf16 g_kwh[1048576], g_kwl[1048576];
__device__ bf16 g_vwh[1048576], g_vwl[1048576];
__device__ bf16 g_owh[2097152], g_owl[2097152];
__device__ bf16 g_w2h[131072],  g_w2l[131072];
__device__ bf16 g_wlh[32768],   g_wll[32768];
__device__ bf16 g_qh[1048576],  g_ql[1048576];
__device__ bf16 g_kh[1048576],  g_kl[1048576];
__device__ bf16 g_vh[1048576],  g_vl[1048576];
__device__ bf16 g_wdh[2097152], g_wdl[2097152];
__device__ bf16 g_Mwh[33554432], g_Mwl[33554432];
__device__ bf16 g_Bh [33554432], g_Bl [33554432];
__device__ bf16 g_QWh[33554432], g_QWl[33554432];
__device__ bf16 g_Tvh[2097152],  g_Tvl[2097152];
__device__ bf16 g_O2h[2097152],  g_O2l[2097152];

__device__ __forceinline__ uint32_t sptr(const void* p) {
    return (uint32_t)__cvta_generic_to_shared(p);
}
__device__ __forceinline__ void ldsm4(uint32_t* r, uint32_t a) {
    asm volatile("ldmatrix.sync.aligned.m8n8.x4.shared.b16 {%0,%1,%2,%3}, [%4];"
        : "=r"(r[0]), "=r"(r[1]), "=r"(r[2]), "=r"(r[3]) : "r"(a));
}
__device__ __forceinline__ void ldsm4t(uint32_t* r, uint32_t a) {
    asm volatile("ldmatrix.sync.aligned.m8n8.x4.trans.shared.b16 {%0,%1,%2,%3}, [%4];"
        : "=r"(r[0]), "=r"(r[1]), "=r"(r[2]), "=r"(r[3]) : "r"(a));
}
__device__ __forceinline__ void mma_bf(float* c, const uint32_t* a, const uint32_t* b) {
    asm volatile(
        "mma.sync.aligned.m16n8k16.row.col.f32.bf16.bf16.f32 "
        "{%0,%1,%2,%3},{%4,%5,%6,%7},{%8,%9},{%0,%1,%2,%3};"
        : "+f"(c[0]), "+f"(c[1]), "+f"(c[2]), "+f"(c[3])
        : "r"(a[0]), "r"(a[1]), "r"(a[2]), "r"(a[3]), "r"(b[0]), "r"(b[1]));
}
__device__ __forceinline__ void st_split2(bf16* hi, bf16* lo, size_t off, float v0, float v1) {
    bf16 h0 = __float2bfloat16(v0), h1 = __float2bfloat16(v1);
    *(__nv_bfloat162*)(hi + off) = __halves2bfloat162(h0, h1);
    *(__nv_bfloat162*)(lo + off) = __halves2bfloat162(
        __float2bfloat16(v0 - __bfloat162float(h0)),
        __float2bfloat16(v1 - __bfloat162float(h1)));
}
__device__ __forceinline__ void cpa16(void* s, const void* g) {
    asm volatile("cp.async.cg.shared.global [%0], [%1], 16;" :: "r"(sptr(s)), "l"(g) : "memory");
}
#define CPC() asm volatile("cp.async.commit_group;" ::: "memory")
#define CPW(n) asm volatile("cp.async.wait_group %0;" :: "n"(n) : "memory")

template<bool TRANSB>
__device__ __forceinline__ void mma_tile(float (&acc)[2][4][4],
    const bf16* sAh, const bf16* sAl, int SA, int arow, int ka0,
    const bf16* sBh, const bf16* sBl, int SB, int bcol, int kb0, int lane)
{
    uint32_t ah[2][4], al[2][4];
    {
        int r = arow + (lane & 15);
        int c = ka0 + ((lane >> 4) << 3);
        ldsm4(ah[0], sptr(sAh + r * SA + c));
        ldsm4(ah[1], sptr(sAh + (r + 16) * SA + c));
        ldsm4(al[0], sptr(sAl + r * SA + c));
        ldsm4(al[1], sptr(sAl + (r + 16) * SA + c));
    }
    uint32_t bh[4][2], bl[4][2];
    int m = lane >> 3, rr = lane & 7;
#pragma unroll
    for (int g = 0; g < 2; g++) {
        uint32_t t[4];
        if (!TRANSB) {
            int n  = bcol + g * 16 + ((m >> 1) << 3) + rr;
            int kk = kb0 + ((m & 1) << 3);
            ldsm4(t, sptr(sBh + n * SB + kk));
            bh[2*g][0]=t[0]; bh[2*g][1]=t[1]; bh[2*g+1][0]=t[2]; bh[2*g+1][1]=t[3];
            ldsm4(t, sptr(sBl + n * SB + kk));
            bl[2*g][0]=t[0]; bl[2*g][1]=t[1]; bl[2*g+1][0]=t[2]; bl[2*g+1][1]=t[3];
        } else {
            int kr = kb0 + ((m & 1) << 3) + rr;
            int nc = bcol + g * 16 + ((m >> 1) << 3);
            ldsm4t(t, sptr(sBh + kr * SB + nc));
            bh[2*g][0]=t[0]; bh[2*g][1]=t[1]; bh[2*g+1][0]=t[2]; bh[2*g+1][1]=t[3];
            ldsm4t(t, sptr(sBl + kr * SB + nc));
            bl[2*g][0]=t[0]; bl[2*g][1]=t[1]; bl[2*g+1][0]=t[2]; bl[2*g+1][1]=t[3];
        }
    }
#pragma unroll
    for (int mi = 0; mi < 2; mi++)
#pragma unroll
        for (int ni = 0; ni < 4; ni++) {
            mma_bf(acc[mi][ni], ah[mi], bh[ni]);
            mma_bf(acc[mi][ni], ah[mi], bl[ni]);
            mma_bf(acc[mi][ni], al[mi], bh[ni]);
        }
}

__device__ __forceinline__ void stage2a(bf16* dh, bf16* dl, int stride,
    const bf16* gh, const bf16* gl, int ld, int rows, int c8, int tid)
{
    for (int i = tid; i < rows * c8; i += 256) {
        int r = i / c8, c = (i - r * c8) * 8;
        cpa16(dh + r * stride + c, gh + (size_t)r * ld + c);
        cpa16(dl + r * stride + c, gl + (size_t)r * ld + c);
    }
}
__device__ __forceinline__ void stage128(bf16* dh, bf16* dl, int stride,
    const bf16* gh, const bf16* gl, int ld, int rows, int c8, int tid)
{
    for (int i = tid; i < rows * c8; i += 128) {
        int r = i / c8, c = (i - r * c8) * 8;
        cpa16(dh + r * stride + c, gh + (size_t)r * ld + c);
        cpa16(dl + r * stride + c, gl + (size_t)r * ld + c);
    }
}

__global__ __launch_bounds__(256)
void split_all(const float* __restrict__ x, const float* __restrict__ qw,
               const float* __restrict__ kw, const float* __restrict__ vw,
               const float* __restrict__ ow, const float* __restrict__ w2) {
    int b = blockIdx.x;
    const float* src; bf16 *hi, *lo; int base;
    if (b < 4096)       { src = x;  hi = g_xh;  lo = g_xl;  base = b; }
    else if (b < 8192)  { src = qw; hi = g_qwh; lo = g_qwl; base = b - 4096; }
    else if (b < 12288) { src = kw; hi = g_kwh; lo = g_kwl; base = b - 8192; }
    else if (b < 16384) { src = vw; hi = g_vwh; lo = g_vwl; base = b - 12288; }
    else if (b < 24576) { src = ow; hi = g_owh; lo = g_owl; base = b - 16384; }
    else                { src = w2; hi = g_w2h; lo = g_w2l; base = b - 24576; }
    int i = base * 256 + threadIdx.x;
    float v = src[i];
    bf16 h = __float2bfloat16(v);
    hi[i] = h;
    lo[i] = __float2bfloat16(v - __bfloat162float(h));
}

// ======== qkv projection body (dynamic smem) ========
__device__ void qkv_body(bf16* sm, int zz, int jt, int it) {
    const int BUF = 15360;
    const bf16 *Bh, *Bl; bf16 *Ch, *Cl;
    if (zz == 0)      { Bh = g_qwh; Bl = g_qwl; Ch = g_qh; Cl = g_ql; }
    else if (zz == 1) { Bh = g_kwh; Bl = g_kwl; Ch = g_kh; Cl = g_kl; }
    else              { Bh = g_vwh; Bl = g_vwl; Ch = g_vh; Cl = g_vl; }
    int tid = threadIdx.x, lane = tid & 31, w = tid >> 5;
    int m0 = it * 128, n0 = jt * 64;
    int arow = (w >> 1) * 32, bcol = (w & 1) * 32;
    float acc[2][4][4] = {};
    auto stg = [&](int b, int k0) {
        bf16* p = sm + b * BUF;
        stage2a(p, p+5120, 40, g_xh + (size_t)m0*1024 + k0, g_xl + (size_t)m0*1024 + k0, 1024, 128, 4, tid);
        stage2a(p+10240, p+12800, 40, Bh + (size_t)n0*1024 + k0, Bl + (size_t)n0*1024 + k0, 1024, 64, 4, tid);
        CPC();
    };
    stg(0, 0);
    for (int i = 0; i < 32; i++) {
        if (i+1 < 32) { stg((i+1)&1, (i+1)*32); CPW(1); } else CPW(0);
        __syncthreads();
        bf16* p = sm + (i&1)*BUF;
        mma_tile<false>(acc, p, p+5120, 40, arow, 0,  p+10240, p+12800, 40, bcol, 0,  lane);
        mma_tile<false>(acc, p, p+5120, 40, arow, 16, p+10240, p+12800, 40, bcol, 16, lane);
        __syncthreads();
    }
    int r0 = arow + (lane >> 2), c0 = bcol + (lane & 3) * 2;
#pragma unroll
    for (int mi = 0; mi < 2; mi++)
#pragma unroll
        for (int ni = 0; ni < 4; ni++)
#pragma unroll
            for (int hf = 0; hf < 2; hf++) {
                int row = m0 + r0 + mi*16 + hf*8;
                int col = n0 + c0 + ni*8;
                st_split2(Ch, Cl, (size_t)row * 1024 + col,
                          acc[mi][ni][hf*2], acc[mi][ni][hf*2+1]);
            }
}

// ======== lowrank body (dynamic smem) ========
__device__ void lowrank_body(float* dyn, int t,
    const float* __restrict__ x, const float* __restrict__ w1,
    const float* __restrict__ btw, const float* __restrict__ btb) {
    float* sx = dyn;            // 1024
    float* red = dyn + 1024;    // 64*5
    int tid = threadIdx.x;
    *(float4*)&sx[tid*4] = *(const float4*)&x[(size_t)t*1024 + tid*4];
    __syncthreads();
    int c = tid & 63, s = tid >> 6;
    const float* w = (c < 32) ? (w1 + (size_t)c*1024) : (btw + (size_t)(c-32)*1024);
    float acc = 0.f;
    for (int k = s*256; k < s*256 + 256; k += 4) {
        float4 wv = *(const float4*)&w[k];
        acc += wv.x*sx[k] + wv.y*sx[k+1] + wv.z*sx[k+2] + wv.w*sx[k+3];
    }
    red[c*5 + s] = acc;
    __syncthreads();
    if (tid < 64) {
        float v = red[tid*5] + red[tid*5+1] + red[tid*5+2] + red[tid*5+3];
        if (tid < 32) {
            bf16 hh = __float2bfloat16(v);
            g_wlh[t*32 + tid] = hh;
            g_wll[t*32 + tid] = __float2bfloat16(v - __bfloat162float(hh));
        } else {
            int hr = tid - 32;
            g_betah[hr*TT + t] = 2.f / (1.f + __expf(-(v + btb[hr])));
        }
    }
}

// ---- merged qkv + lowrank launch: z<3 qkv, z>=3 lowrank ----
__global__ __launch_bounds__(256)
void tc_qkv_lr(const float* __restrict__ x, const float* __restrict__ w1,
               const float* __restrict__ btw, const float* __restrict__ btb) {
    extern __shared__ __align__(16) bf16 sm[];
    int z = blockIdx.z;
    if (z < 3) qkv_body(sm, z, blockIdx.x, blockIdx.y);
    else {
        int t = (z - 3) * 128 + blockIdx.y * 16 + blockIdx.x;
        lowrank_body((float*)sm, t, x, w1, btw, btb);
    }
}

// ---- wraw = wlow @ w2^T on tensor cores ----
__global__ __launch_bounds__(256)
void tc_wraw() {
    __shared__ __align__(16) bf16 sA[15360];
    int tid = threadIdx.x, lane = tid & 31, w = tid >> 5;
    int m0 = blockIdx.y * 128, n0 = blockIdx.x * 64;
    int arow = (w >> 1) * 32, bcol = (w & 1) * 32;
    float acc[2][4][4] = {};
    stage2a(sA, sA+5120, 40, g_wlh + (size_t)m0*32, g_wll + (size_t)m0*32, 32, 128, 4, tid);
    stage2a(sA+10240, sA+12800, 40, g_w2h + (size_t)n0*32, g_w2l + (size_t)n0*32, 32, 64, 4, tid);
    CPC(); CPW(0);
    __syncthreads();
    mma_tile<false>(acc, sA, sA+5120, 40, arow, 0,  sA+10240, sA+12800, 40, bcol, 0,  lane);
    mma_tile<false>(acc, sA, sA+5120, 40, arow, 16, sA+10240, sA+12800, 40, bcol, 16, lane);
    int r0 = arow + (lane >> 2), c0 = bcol + (lane & 3) * 2;
#pragma unroll
    for (int mi = 0; mi < 2; mi++)
#pragma unroll
        for (int ni = 0; ni < 4; ni++)
#pragma unroll
            for (int hf = 0; hf < 2; hf++) {
                int row = m0 + r0 + mi*16 + hf*8;
                int col = n0 + c0 + ni*8;
                *(float2*)&g_wraw[(size_t)row * 4096 + col] =
                    make_float2(acc[mi][ni][hf*2], acc[mi][ni][hf*2+1]);
            }
}

// ---- dense out-projection ----
__global__ __launch_bounds__(256)
void tc_dense(const bf16* __restrict__ Ah, const bf16* __restrict__ Al, int lda,
              const bf16* __restrict__ Bh, const bf16* __restrict__ Bl, int ldb,
              int K, float* __restrict__ Cf, int ldc)
{
    extern __shared__ __align__(16) bf16 sm[];
    const int BUF = 15360;
    int tid = threadIdx.x, lane = tid & 31, w = tid >> 5;
    int m0 = blockIdx.y * 128, n0 = blockIdx.x * 64;
    int arow = (w >> 1) * 32, bcol = (w & 1) * 32;
    float acc[2][4][4] = {};
    int nk = K / 32;
    auto stg = [&](int b, int k0) {
        bf16* p = sm + b * BUF;
        stage2a(p, p+5120, 40, Ah + (size_t)m0*lda + k0, Al + (size_t)m0*lda + k0, lda, 128, 4, tid);
        stage2a(p+10240, p+12800, 40, Bh + (size_t)n0*ldb + k0, Bl + (size_t)n0*ldb + k0, ldb, 64, 4, tid);
        CPC();
    };
    stg(0, 0);
    for (int i = 0; i < nk; i++) {
        if (i+1 < nk) { stg((i+1)&1, (i+1)*32); CPW(1); } else CPW(0);
        __syncthreads();
        bf16* p = sm + (i&1)*BUF;
        mma_tile<false>(acc, p, p+5120, 40, arow, 0,  p+10240, p+12800, 40, bcol, 0,  lane);
        mma_tile<false>(acc, p, p+5120, 40, arow, 16, p+10240, p+12800, 40, bcol, 16, lane);
        __syncthreads();
    }
    int r0 = arow + (lane >> 2), c0 = bcol + (lane & 3) * 2;
#pragma unroll
    for (int mi = 0; mi < 2; mi++)
#pragma unroll
        for (int ni = 0; ni < 4; ni++)
#pragma unroll
            for (int hf = 0; hf < 2; hf++) {
                int row = m0 + r0 + mi*16 + hf*8;
                int col = n0 + c0 + ni*8;
                *(float2*)&Cf[(size_t)row * ldc + col] =
                    make_float2(acc[mi][ni][hf*2], acc[mi][ni][hf*2+1]);
            }
}

// ======== per-head GEMM body (stages 0..3), dynamic smem ========
__device__ void headz_body(bf16* sm, int stage, int h, int jt, int it) {
    const bf16 *Ahp, *Alp, *Bhp, *Blp;
    int lda, ldb, mode;
    const float* rowscale = nullptr;
    if (stage == 0) {
        Ahp = g_wdh + (size_t)h*65536; Alp = g_wdl + (size_t)h*65536; lda = 64;
        Bhp = g_wdh + (size_t)h*65536; Blp = g_wdl + (size_t)h*65536; ldb = 64;
        mode = 1; rowscale = g_betah;
    } else if (stage == 1) {
        Ahp = g_wdh + (size_t)h*65536; Alp = g_wdl + (size_t)h*65536; lda = 64;
        Bhp = g_kh + (size_t)(h>>1)*64; Blp = g_kl + (size_t)(h>>1)*64; ldb = 1024;
        mode = 1; rowscale = g_betah;
    } else if (stage == 2) {
        Ahp = g_qh + (size_t)h*64; Alp = g_ql + (size_t)h*64; lda = 1024;
        Bhp = g_kh + (size_t)h*64; Blp = g_kl + (size_t)h*64; ldb = 1024;
        mode = 2;
    } else {
        Ahp = g_qh + (size_t)(h>>1)*64; Alp = g_ql + (size_t)(h>>1)*64; lda = 1024;
        Bhp = g_wdh + (size_t)h*65536; Blp = g_wdl + (size_t)h*65536; ldb = 64;
        mode = 2;
    }
    Ahp += (size_t)(it*128) * lda; Alp += (size_t)(it*128) * lda;
    Bhp += (size_t)(jt*64)  * ldb; Blp += (size_t)(jt*64)  * ldb;

    const int BUF = 15360;
    int tid = threadIdx.x, lane = tid & 31, w = tid >> 5;
    int arow = (w >> 1) * 32, bcol = (w & 1) * 32;
    float acc[2][4][4] = {};
    auto stg = [&](int b, int k0) {
        bf16* p = sm + b * BUF;
        stage2a(p, p+5120, 40, Ahp + k0, Alp + k0, lda, 128, 4, tid);
        stage2a(p+10240, p+12800, 40, Bhp + k0, Blp + k0, ldb, 64, 4, tid);
        CPC();
    };
    stg(0, 0);
#pragma unroll
    for (int i = 0; i < 2; i++) {
        if (i == 0) { stg(1, 32); CPW(1); } else CPW(0);
        __syncthreads();
        bf16* p = sm + i*BUF;
        mma_tile<false>(acc, p, p+5120, 40, arow, 0,  p+10240, p+12800, 40, bcol, 0,  lane);
        mma_tile<false>(acc, p, p+5120, 40, arow, 16, p+10240, p+12800, 40, bcol, 16, lane);
        __syncthreads();
    }
    int r0 = arow + (lane >> 2), c0 = bcol + (lane & 3) * 2;
    size_t hb = (size_t)h * HS;
#pragma unroll
    for (int mi = 0; mi < 2; mi++)
#pragma unroll
        for (int ni = 0; ni < 4; ni++)
#pragma unroll
            for (int hf = 0; hf < 2; hf++) {
                int row = it*128 + r0 + mi*16 + hf*8;
                int col = jt*64 + c0 + ni*8;
                float v0 = acc[mi][ni][hf*2], v1 = acc[mi][ni][hf*2+1];
                float sc = rowscale ? rowscale[h * TT + row] : 1.f;
                v0 *= sc; v1 *= sc;
                if (mode == 1) { if (col   >= row) v0 = 0.f;
                                 if (col+1 >= row) v1 = 0.f; }
                else           { if (col   >  row) v0 = 0.f;
                                 if (col+1 >  row) v1 = 0.f; }
                size_t off = hb + (size_t)row * TT + col;
                if (stage == 0)      st_split2(g_Mwh, g_Mwl, off, v0, v1);
                else if (stage == 1) *(float2*)&g_rhs[off] = make_float2(v0, v1);
                else if (stage == 2) *(float2*)&g_QK[off]  = make_float2(v0, v1);
                else                 st_split2(g_QWh, g_QWl, off, v0, v1);
            }
}

// ---- headz stages 0+1 (Mw, rhs): z<32 stage0, z<64 stage1 ----
__global__ __launch_bounds__(256)
void tc_headz01() {
    int jt = blockIdx.x, it = blockIdx.y, z = blockIdx.z;
    if (jt > 2 * it + 1) return;
    extern __shared__ __align__(16) bf16 sm[];
    int stage = (z < 32) ? 0 : 1;
    int h = (z < 32) ? z : z - 32;
    headz_body(sm, stage, h, jt, it);
}

__global__ __launch_bounds__(64)
void compute_tinv() {
    __shared__ float L[64][65];
    __shared__ float X[64][65];
    int ch = blockIdx.x, h = blockIdx.y, c = threadIdx.x;
    size_t base = (size_t)h * HS + (size_t)(ch*64) * TT + ch*64;
    for (int r = 0; r < 64; r++) {
        L[r][c] = __bfloat162float(g_Mwh[base + (size_t)r*TT + c]) +
                  __bfloat162float(g_Mwl[base + (size_t)r*TT + c]);
        X[r][c] = (r == c) ? 1.f : 0.f;
    }
    __syncthreads();
    for (int r = 1; r < 64; r++) {
        if (c < r) {
            float acc = 0.f;
            for (int s = c; s < r; s++) acc += L[r][s] * X[s][c];
            X[r][c] = -acc;
        }
        __syncthreads();
    }
    size_t ob = ((size_t)(h*16 + ch)) * 4096;
    for (int r = 0; r < 64; r++) {
        float v = X[r][c];
        bf16 hh = __float2bfloat16(v);
        g_Tvh[ob + r*64 + c] = hh;
        g_Tvl[ob + r*64 + c] = __float2bfloat16(v - __bfloat162float(hh));
    }
}

// ======== solve body (one column block, all chunks), dynamic smem ========
__device__ void solve_body(bf16* sm, int jb, int h) {
    const int BUF = 13824;
    int tid = threadIdx.x, lane = tid & 31, w = tid >> 5;
    int arow = (w >> 2) * 32, bcol = (w & 3) * 32;
    size_t hb = (size_t)h * HS;
    int r0 = arow + (lane >> 2), c0 = bcol + (lane & 3) * 2;

    for (int ci = 2*jb; ci < 16; ci++) {
        float acc[2][4][4];
#pragma unroll
        for (int mi = 0; mi < 2; mi++)
#pragma unroll
            for (int ni = 0; ni < 4; ni++)
#pragma unroll
                for (int hf = 0; hf < 2; hf++) {
                    float2 v = *(const float2*)&g_rhs[hb +
                        (size_t)(ci*64 + r0 + mi*16 + hf*8) * TT + jb*128 + c0 + ni*8];
                    acc[mi][ni][hf*2]   = -v.x;
                    acc[mi][ni][hf*2+1] = -v.y;
                }
        int nch = 2 * (ci - 2*jb);
        auto stg = [&](int b, int m) {
            int s = 2*jb + (m >> 1), kc = (m & 1) * 32;
            bf16* p = sm + b * BUF;
            stage2a(p, p+2560, 40,
                    g_Mwh + hb + (size_t)(ci*64)*TT + s*64 + kc,
                    g_Mwl + hb + (size_t)(ci*64)*TT + s*64 + kc, TT, 64, 4, tid);
            stage2a(p+5120, p+9472, 136,
                    g_Bh + hb + (size_t)(s*64 + kc)*TT + jb*128,
                    g_Bl + hb + (size_t)(s*64 + kc)*TT + jb*128, TT, 32, 16, tid);
            CPC();
        };
        if (nch > 0) stg(0, 0);
        for (int m = 0; m < nch; m++) {
            if (m+1 < nch) { stg((m+1)&1, m+1); CPW(1); } else CPW(0);
            __syncthreads();
            bf16* p = sm + (m&1)*BUF;
            mma_tile<true>(acc, p, p+2560, 40, arow, 0,  p+5120, p+9472, 136, bcol, 0,  lane);
            mma_tile<true>(acc, p, p+2560, 40, arow, 16, p+5120, p+9472, 136, bcol, 16, lane);
            __syncthreads();
        }
        bf16 *sPh = sm, *sPl = sm + 8704, *sTh = sm + 17408, *sTl = sm + 19968;
        __syncthreads();
#pragma unroll
        for (int mi = 0; mi < 2; mi++)
#pragma unroll
            for (int ni = 0; ni < 4; ni++)
#pragma unroll
                for (int hf = 0; hf < 2; hf++) {
                    int r = r0 + mi*16 + hf*8, c = c0 + ni*8;
                    st_split2(sPh, sPl, (size_t)r*136 + c,
                              -acc[mi][ni][hf*2], -acc[mi][ni][hf*2+1]);
                }
#pragma unroll
        for (int mi = 0; mi < 2; mi++)
#pragma unroll
            for (int ni = 0; ni < 4; ni++)
#pragma unroll
                for (int e = 0; e < 4; e++) acc[mi][ni][e] = 0.f;
        size_t tb = ((size_t)(h*16 + ci)) * 4096;
#pragma unroll
        for (int kc = 0; kc < 64; kc += 32) {
            stage2a(sTh, sTl, 40, g_Tvh + tb + kc, g_Tvl + tb + kc, 64, 64, 4, tid);
            CPC(); CPW(0);
            __syncthreads();
            mma_tile<true>(acc, sTh, sTl, 40, arow, 0,  sPh, sPl, 136, bcol, kc,      lane);
            mma_tile<true>(acc, sTh, sTl, 40, arow, 16, sPh, sPl, 136, bcol, kc + 16, lane);
            __syncthreads();
        }
#pragma unroll
        for (int mi = 0; mi < 2; mi++)
#pragma unroll
            for (int ni = 0; ni < 4; ni++)
#pragma unroll
                for (int hf = 0; hf < 2; hf++) {
                    int row = ci*64 + r0 + mi*16 + hf*8;
                    int col = jb*128 + c0 + ni*8;
                    st_split2(g_Bh, g_Bl, hb + (size_t)row*TT + col,
                              acc[mi][ni][hf*2], acc[mi][ni][hf*2+1]);
                }
        __syncthreads();
    }
}

// ---- merged launch: solve (z<2, scheduled first) + QK (z 2..17) + QW (z 18..49) ----
__global__ __launch_bounds__(256)
void tc_mix() {
    extern __shared__ __align__(16) bf16 sm[];
    int z = blockIdx.z;
    if (z < 2) {
        int idx = z * 128 + blockIdx.y * 16 + blockIdx.x;   // 0..255
        solve_body(sm, idx & 7, idx >> 3);
    } else {
        int jt = blockIdx.x, it = blockIdx.y;
        if (jt > 2 * it + 1) return;
        int zz = z - 2;
        int stage = (zz < 16) ? 2 : 3;
        int h = (zz < 16) ? zz : zz - 16;
        headz_body(sm, stage, h, jt, it);
    }
}

// ==== flash-fused attention: logits + online softmax + PV, split-K over jt ====
__global__ __launch_bounds__(128)
void tc_attn() {
    extern __shared__ __align__(16) bf16 sm[];
    const int BUF = 9728;
    bf16* sPh = sm + 19456;
    bf16* sPl = sm + 24064;
    float* sMrow = (float*)(sm + 28672);
    float* sSrow = sMrow + 64;
    float* sPmax = sSrow + 64;
    float* sPsum = sPmax + 128;
    int it = 15 - blockIdx.x, p = blockIdx.y, h = blockIdx.z;
    int tid = threadIdx.x, lane = tid & 31, w = tid >> 5;
    int arow = (w >> 1) * 32, bcol = (w & 1) * 32;
    int rl0 = arow + (lane >> 2), cl0 = bcol + (lane & 3) * 2;
    size_t hb = (size_t)h * HS;
    size_t qb = (size_t)(h >> 1) * HS;
    for (int i = tid; i < 64; i += 128) { sMrow[i] = -1e30f; sSrow[i] = 0.f; }
    float o[2][4][4];
#pragma unroll
    for (int mi = 0; mi < 2; mi++)
#pragma unroll
        for (int ni = 0; ni < 4; ni++)
#pragma unroll
            for (int e = 0; e < 4; e++) o[mi][ni][e] = 0.f;
    __syncthreads();

    for (int jt = p; jt <= it; jt += 2) {
        float acc[2][4][4] = {};
        int nch = 2 * (it - jt + 1);
        auto stg = [&](int b, int m) {
            int kb = jt + (m >> 1), kc = (m & 1) * 32;
            bf16* pp = sm + b * BUF;
            stage128(pp, pp+2560, 40,
                g_QWh + hb + (size_t)(it*64)*TT + kb*64 + kc,
                g_QWl + hb + (size_t)(it*64)*TT + kb*64 + kc, TT, 64, 4, tid);
            stage128(pp+5120, pp+7424, 72,
                g_Bh + hb + (size_t)(kb*64 + kc)*TT + jt*64,
                g_Bl + hb + (size_t)(kb*64 + kc)*TT + jt*64, TT, 32, 8, tid);
            CPC();
        };
        stg(0, 0);
        for (int m = 0; m < nch; m++) {
            if (m+1 < nch) { stg((m+1)&1, m+1); CPW(1); } else CPW(0);
            __syncthreads();
            bf16* pp = sm + (m&1)*BUF;
            mma_tile<true>(acc, pp, pp+2560, 40, arow, 0,  pp+5120, pp+7424, 72, bcol, 0,  lane);
            mma_tile<true>(acc, pp, pp+2560, 40, arow, 16, pp+5120, pp+7424, 72, bcol, 16, lane);
            __syncthreads();
        }
        float pmv[2][2];
#pragma unroll
        for (int mi = 0; mi < 2; mi++)
#pragma unroll
            for (int hf = 0; hf < 2; hf++) {
                int rl = rl0 + mi*16 + hf*8;
                int row_g = it*64 + rl;
                float best = -1e30f;
#pragma unroll
                for (int ni = 0; ni < 4; ni++) {
                    int col_g = jt*64 + cl0 + ni*8;
                    float2 q = *(const float2*)&g_QK[qb + (size_t)row_g*TT + col_g];
                    float L0 = (q.x - acc[mi][ni][hf*2])   * ATT_SCALE;
                    float L1 = (q.y - acc[mi][ni][hf*2+1]) * ATT_SCALE;
                    if (jt == it) {
                        if (col_g     > row_g) L0 = -1e30f;
                        if (col_g + 1 > row_g) L1 = -1e30f;
                    }
                    acc[mi][ni][hf*2]   = L0;
                    acc[mi][ni][hf*2+1] = L1;
                    best = fmaxf(best, fmaxf(L0, L1));
                }
                pmv[mi][hf] = best;
            }
#pragma unroll
        for (int mi = 0; mi < 2; mi++)
#pragma unroll
            for (int hf = 0; hf < 2; hf++) {
                float v = pmv[mi][hf];
                v = fmaxf(v, __shfl_xor_sync(~0u, v, 1));
                v = fmaxf(v, __shfl_xor_sync(~0u, v, 2));
                pmv[mi][hf] = v;
            }
        if ((lane & 3) == 0)
#pragma unroll
            for (int mi = 0; mi < 2; mi++)
#pragma unroll
                for (int hf = 0; hf < 2; hf++)
                    sPmax[(rl0 + mi*16 + hf*8)*2 + (w & 1)] = pmv[mi][hf];
        __syncthreads();
        float psv[2][2];
#pragma unroll
        for (int mi = 0; mi < 2; mi++)
#pragma unroll
            for (int hf = 0; hf < 2; hf++) {
                int rl = rl0 + mi*16 + hf*8;
                float mo = sMrow[rl];
                float m2 = fmaxf(mo, fmaxf(sPmax[rl*2], sPmax[rl*2+1]));
                float f = __expf(mo - m2);
                float sum = 0.f;
#pragma unroll
                for (int ni = 0; ni < 4; ni++) {
                    float e0 = __expf(acc[mi][ni][hf*2]   - m2);
                    float e1 = __expf(acc[mi][ni][hf*2+1] - m2);
                    acc[mi][ni][hf*2] = e0; acc[mi][ni][hf*2+1] = e1;
                    sum += e0 + e1;
                    o[mi][ni][hf*2]   *= f;
                    o[mi][ni][hf*2+1] *= f;
                    st_split2(sPh, sPl, (size_t)rl*72 + cl0 + ni*8, e0, e1);
                }
                psv[mi][hf] = sum;
            }
#pragma unroll
        for (int mi = 0; mi < 2; mi++)
#pragma unroll
            for (int hf = 0; hf < 2; hf++) {
                float v = psv[mi][hf];
                v += __shfl_xor_sync(~0u, v, 1);
                v += __shfl_xor_sync(~0u, v, 2);
                psv[mi][hf] = v;
            }
        if ((lane & 3) == 0)
#pragma unroll
            for (int mi = 0; mi < 2; mi++)
#pragma unroll
                for (int hf = 0; hf < 2; hf++)
                    sPsum[(rl0 + mi*16 + hf*8)*2 + (w & 1)] = psv[mi][hf];
        stage128(sm, sm + 4608, 72,
                 g_vh + (size_t)(jt*64)*1024 + (size_t)(h>>1)*64,
                 g_vl + (size_t)(jt*64)*1024 + (size_t)(h>>1)*64, 1024, 64, 8, tid);
        CPC();
        __syncthreads();
        if (tid < 64) {
            float mo = sMrow[tid];
            float m2 = fmaxf(mo, fmaxf(sPmax[tid*2], sPmax[tid*2+1]));
            float f = __expf(mo - m2);
            sSrow[tid] = sSrow[tid] * f + sPsum[tid*2] + sPsum[tid*2+1];
            sMrow[tid] = m2;
        }
        CPW(0);
        __syncthreads();
#pragma unroll
        for (int mi = 0; mi < 2; mi++)
#pragma unroll
            for (int ni = 0; ni < 4; ni++)
#pragma unroll
                for (int e = 0; e < 4; e++) acc[mi][ni][e] = 0.f;
        mma_tile<true>(acc, sPh, sPl, 72, arow, 0,  sm, sm+4608, 72, bcol, 0,  lane);
        mma_tile<true>(acc, sPh, sPl, 72, arow, 16, sm, sm+4608, 72, bcol, 16, lane);
        mma_tile<true>(acc, sPh, sPl, 72, arow, 32, sm, sm+4608, 72, bcol, 32, lane);
        mma_tile<true>(acc, sPh, sPl, 72, arow, 48, sm, sm+4608, 72, bcol, 48, lane);
#pragma unroll
        for (int mi = 0; mi < 2; mi++)
#pragma unroll
            for (int ni = 0; ni < 4; ni++)
#pragma unroll
                for (int e = 0; e < 4; e++) o[mi][ni][e] += acc[mi][ni][e];
        __syncthreads();
    }
    float* PB = g_rhs + ((size_t)((h*16 + it)*2 + p)) * 4224;
#pragma unroll
    for (int mi = 0; mi < 2; mi++)
#pragma unroll
        for (int ni = 0; ni < 4; ni++)
#pragma unroll
            for (int hf = 0; hf < 2; hf++) {
                int rl = rl0 + mi*16 + hf*8;
                *(float2*)&PB[rl*64 + cl0 + ni*8] =
                    make_float2(o[mi][ni][hf*2], o[mi][ni][hf*2+1]);
            }
    if (tid < 64) { PB[4096 + tid] = sMrow[tid]; PB[4160 + tid] = sSrow[tid]; }
}

__global__ __launch_bounds__(128)
void attn_merge() {
    int it = blockIdx.x, h = blockIdx.y, tid = threadIdx.x;
    const float* P0 = g_rhs + ((size_t)((h*16 + it)*2)) * 4224;
    const float* P1 = P0 + 4224;
    __shared__ float w0[64], w1[64], inv[64];
    if (tid < 64) {
        float m0 = P0[4096+tid], m1 = P1[4096+tid];
        float mm = fmaxf(m0, m1);
        float e0 = __expf(m0 - mm), e1 = __expf(m1 - mm);
        float s = P0[4160+tid]*e0 + P1[4160+tid]*e1;
        w0[tid] = e0; w1[tid] = e1; inv[tid] = 1.f / s;
    }
    __syncthreads();
    for (int i = tid; i < 4096; i += 128) {
        int r = i >> 6, c = i & 63;
        float v = (P0[i]*w0[r] + P1[i]*w1[r]) * inv[r];
        size_t off = (size_t)(it*64 + r) * 2048 + h*64 + c;
        bf16 hh = __float2bfloat16(v);
        g_O2h[off] = hh;
        g_O2l[off] = __float2bfloat16(v - __bfloat162float(hh));
    }
}

__global__ __launch_bounds__(64)
void wdir_kernel(const float* __restrict__ wraw, const float* __restrict__ conv_w,
                 const float* __restrict__ omega, const float* __restrict__ phi) {
    int t = blockIdx.x, hr = blockIdx.y, d = threadIdx.x;
    int hkv = hr >> 1, r = hr & 1;
    int cA = hkv * 256 + (2*r) * 64 + d;
    int cB = cA + 64;
    float a = 0.f, b = 0.f;
#pragma unroll
    for (int i = 0; i < 3; i++) {
        int tt = t + i - 2;
        if (tt >= 0) {
            a += wraw[(size_t)tt * 4096 + cA] * conv_w[cA*3 + i];
            b += wraw[(size_t)tt * 4096 + cB] * conv_w[cB*3 + i];
        }
    }
    a = a / (1.f + expf(-a));
    b = b / (1.f + expf(-b));
    float th = omega[r] * (float)t + phi[r];
    float w = a * cosf(th) + b * sinf(th);
    float ss = w * w;
#pragma unroll
    for (int o = 16; o; o >>= 1) ss += __shfl_xor_sync(~0u, ss, o);
    __shared__ float sh[2];
    if ((d & 31) == 0) sh[d >> 5] = ss;
    __syncthreads();
    float tot = sh[0] + sh[1];
    float val = w * rsqrtf(tot + 1e-6f);
    size_t off = ((size_t)hr * TT + t) * 64 + d;
    bf16 hh = __float2bfloat16(val);
    g_wdh[off] = hh;
    g_wdl[off] = __float2bfloat16(val - __bfloat162float(hh));
}

#define GS(p, s) cudaGetSymbolAddress((void**)&p, s)

extern "C" void kernel_launch(void* const* d_in, const int* in_sizes, int n_in,
                              void* d_out, int out_size) {
    const float* x    = (const float*)d_in[0];
    const float* q_w  = (const float*)d_in[1];
    const float* k_w  = (const float*)d_in[2];
    const float* v_w  = (const float*)d_in[3];
    const float* w1   = (const float*)d_in[4];
    const float* w2   = (const float*)d_in[5];
    const float* cw   = (const float*)d_in[6];
    const float* btw  = (const float*)d_in[7];
    const float* btb  = (const float*)d_in[8];
    const float* ow   = (const float*)d_in[9];
    const float* omega= (const float*)d_in[10];
    const float* phi  = (const float*)d_in[11];
    float* out = (float*)d_out;

    float* pwraw;
    bf16 *pO2h,*pO2l,*powh,*powl;
    GS(pwraw,g_wraw);
    GS(pO2h,g_O2h); GS(pO2l,g_O2l); GS(powh,g_owh); GS(powl,g_owl);

    static bool attr_done = false;
    if (!attr_done) {
        cudaFuncSetAttribute(tc_dense,   cudaFuncAttributeMaxDynamicSharedMemorySize, 61440);
        cudaFuncSetAttribute(tc_qkv_lr,  cudaFuncAttributeMaxDynamicSharedMemorySize, 61440);
        cudaFuncSetAttribute(tc_headz01, cudaFuncAttributeMaxDynamicSharedMemorySize, 61440);
        cudaFuncSetAttribute(tc_mix,     cudaFuncAttributeMaxDynamicSharedMemorySize, 61440);
        cudaFuncSetAttribute(tc_attn,    cudaFuncAttributeMaxDynamicSharedMemorySize, 58880);
        attr_done = true;
    }

    split_all<<<25088, 256>>>(x, q_w, k_w, v_w, ow, w2);

    // qkv (z<3) merged with lowrank (z 3..10)
    tc_qkv_lr<<<dim3(16,8,11), 256, 61440>>>(x, w1, btw, btb);
    tc_wraw<<<dim3(64,8), 256>>>();
    wdir_kernel<<<dim3(1024, 32), 64>>>(pwraw, cw, omega, phi);

    // Mw + rhs
    tc_headz01<<<dim3(16,8,64), 256, 61440>>>();
    compute_tinv<<<dim3(16,32), 64>>>();

    // merged: solve (z<2) + QK (z 2..17) + QW (z 18..49)
    tc_mix<<<dim3(16,8,50), 256, 61440>>>();

    tc_attn<<<dim3(16,2,32), 128, 58880>>>();
    attn_merge<<<dim3(16,32), 128>>>();

    tc_dense<<<dim3(16,8), 256, 61440>>>(pO2h, pO2l, 2048, powh, powl, 2048, 2048,
                                         out, 1024);
}

// round 16
// speedup vs baseline: 1.0979x; 1.0040x over previous
#include <cuda_runtime.h>
#include <cuda_bf16.h>
#include <cstdint>

using bf16 = __nv_bfloat16;
#define TT 1024
#define HS 1048576
#define ATT_SCALE 0.125f

__device__ float g_wraw[TT*4096];
__device__ float g_betah[32*TT];
__device__ float g_rhs[32*HS];
__device__ float g_QK [16*HS];

__device__ bf16 g_xh[1048576],  g_xl[1048576];
__device__ bf16 g_qwh[1048576], g_qwl[1048576];
__device__ bf16 g_kwh[1048576], g_kwl[1048576];
__device__ bf16 g_vwh[1048576], g_vwl[1048576];
__device__ bf16 g_owh[2097152], g_owl[2097152];
__device__ bf16 g_w2h[131072],  g_w2l[131072];
__device__ bf16 g_wlh[32768],   g_wll[32768];
__device__ bf16 g_qh[1048576],  g_ql[1048576];
__device__ bf16 g_kh[1048576],  g_kl[1048576];
__device__ bf16 g_vh[1048576],  g_vl[1048576];
__device__ bf16 g_wdh[2097152], g_wdl[2097152];
__device__ bf16 g_Mwh[33554432], g_Mwl[33554432];
__device__ bf16 g_Bh [33554432], g_Bl [33554432];
__device__ bf16 g_QWh[33554432], g_QWl[33554432];
__device__ bf16 g_Tvh[2097152],  g_Tvl[2097152];
__device__ bf16 g_O2h[2097152],  g_O2l[2097152];

__device__ __forceinline__ uint32_t sptr(const void* p) {
    return (uint32_t)__cvta_generic_to_shared(p);
}
__device__ __forceinline__ void ldsm4(uint32_t* r, uint32_t a) {
    asm volatile("ldmatrix.sync.aligned.m8n8.x4.shared.b16 {%0,%1,%2,%3}, [%4];"
        : "=r"(r[0]), "=r"(r[1]), "=r"(r[2]), "=r"(r[3]) : "r"(a));
}
__device__ __forceinline__ void ldsm4t(uint32_t* r, uint32_t a) {
    asm volatile("ldmatrix.sync.aligned.m8n8.x4.trans.shared.b16 {%0,%1,%2,%3}, [%4];"
        : "=r"(r[0]), "=r"(r[1]), "=r"(r[2]), "=r"(r[3]) : "r"(a));
}
__device__ __forceinline__ void mma_bf(float* c, const uint32_t* a, const uint32_t* b) {
    asm volatile(
        "mma.sync.aligned.m16n8k16.row.col.f32.bf16.bf16.f32 "
        "{%0,%1,%2,%3},{%4,%5,%6,%7},{%8,%9},{%0,%1,%2,%3};"
        : "+f"(c[0]), "+f"(c[1]), "+f"(c[2]), "+f"(c[3])
        : "r"(a[0]), "r"(a[1]), "r"(a[2]), "r"(a[3]), "r"(b[0]), "r"(b[1]));
}
__device__ __forceinline__ void st_split2(bf16* hi, bf16* lo, size_t off, float v0, float v1) {
    bf16 h0 = __float2bfloat16(v0), h1 = __float2bfloat16(v1);
    *(__nv_bfloat162*)(hi + off) = __halves2bfloat162(h0, h1);
    *(__nv_bfloat162*)(lo + off) = __halves2bfloat162(
        __float2bfloat16(v0 - __bfloat162float(h0)),
        __float2bfloat16(v1 - __bfloat162float(h1)));
}
__device__ __forceinline__ void cpa16(void* s, const void* g) {
    asm volatile("cp.async.cg.shared.global [%0], [%1], 16;" :: "r"(sptr(s)), "l"(g) : "memory");
}
#define CPC() asm volatile("cp.async.commit_group;" ::: "memory")
#define CPW(n) asm volatile("cp.async.wait_group %0;" :: "n"(n) : "memory")

template<bool TRANSB>
__device__ __forceinline__ void mma_tile(float (&acc)[2][4][4],
    const bf16* sAh, const bf16* sAl, int SA, int arow, int ka0,
    const bf16* sBh, const bf16* sBl, int SB, int bcol, int kb0, int lane)
{
    uint32_t ah[2][4], al[2][4];
    {
        int r = arow + (lane & 15);
        int c = ka0 + ((lane >> 4) << 3);
        ldsm4(ah[0], sptr(sAh + r * SA + c));
        ldsm4(ah[1], sptr(sAh + (r + 16) * SA + c));
        ldsm4(al[0], sptr(sAl + r * SA + c));
        ldsm4(al[1], sptr(sAl + (r + 16) * SA + c));
    }
    uint32_t bh[4][2], bl[4][2];
    int m = lane >> 3, rr = lane & 7;
#pragma unroll
    for (int g = 0; g < 2; g++) {
        uint32_t t[4];
        if (!TRANSB) {
            int n  = bcol + g * 16 + ((m >> 1) << 3) + rr;
            int kk = kb0 + ((m & 1) << 3);
            ldsm4(t, sptr(sBh + n * SB + kk));
            bh[2*g][0]=t[0]; bh[2*g][1]=t[1]; bh[2*g+1][0]=t[2]; bh[2*g+1][1]=t[3];
            ldsm4(t, sptr(sBl + n * SB + kk));
            bl[2*g][0]=t[0]; bl[2*g][1]=t[1]; bl[2*g+1][0]=t[2]; bl[2*g+1][1]=t[3];
        } else {
            int kr = kb0 + ((m & 1) << 3) + rr;
            int nc = bcol + g * 16 + ((m >> 1) << 3);
            ldsm4t(t, sptr(sBh + kr * SB + nc));
            bh[2*g][0]=t[0]; bh[2*g][1]=t[1]; bh[2*g+1][0]=t[2]; bh[2*g+1][1]=t[3];
            ldsm4t(t, sptr(sBl + kr * SB + nc));
            bl[2*g][0]=t[0]; bl[2*g][1]=t[1]; bl[2*g+1][0]=t[2]; bl[2*g+1][1]=t[3];
        }
    }
#pragma unroll
    for (int mi = 0; mi < 2; mi++)
#pragma unroll
        for (int ni = 0; ni < 4; ni++) {
            mma_bf(acc[mi][ni], ah[mi], bh[ni]);
            mma_bf(acc[mi][ni], ah[mi], bl[ni]);
            mma_bf(acc[mi][ni], al[mi], bh[ni]);
        }
}

__device__ __forceinline__ void stage2a(bf16* dh, bf16* dl, int stride,
    const bf16* gh, const bf16* gl, int ld, int rows, int c8, int tid)
{
    for (int i = tid; i < rows * c8; i += 256) {
        int r = i / c8, c = (i - r * c8) * 8;
        cpa16(dh + r * stride + c, gh + (size_t)r * ld + c);
        cpa16(dl + r * stride + c, gl + (size_t)r * ld + c);
    }
}
__device__ __forceinline__ void stage128(bf16* dh, bf16* dl, int stride,
    const bf16* gh, const bf16* gl, int ld, int rows, int c8, int tid)
{
    for (int i = tid; i < rows * c8; i += 128) {
        int r = i / c8, c = (i - r * c8) * 8;
        cpa16(dh + r * stride + c, gh + (size_t)r * ld + c);
        cpa16(dl + r * stride + c, gl + (size_t)r * ld + c);
    }
}

__global__ __launch_bounds__(256)
void split_all(const float* __restrict__ x, const float* __restrict__ qw,
               const float* __restrict__ kw, const float* __restrict__ vw,
               const float* __restrict__ ow, const float* __restrict__ w2) {
    int b = blockIdx.x;
    const float* src; bf16 *hi, *lo; int base;
    if (b < 4096)       { src = x;  hi = g_xh;  lo = g_xl;  base = b; }
    else if (b < 8192)  { src = qw; hi = g_qwh; lo = g_qwl; base = b - 4096; }
    else if (b < 12288) { src = kw; hi = g_kwh; lo = g_kwl; base = b - 8192; }
    else if (b < 16384) { src = vw; hi = g_vwh; lo = g_vwl; base = b - 12288; }
    else if (b < 24576) { src = ow; hi = g_owh; lo = g_owl; base = b - 16384; }
    else                { src = w2; hi = g_w2h; lo = g_w2l; base = b - 24576; }
    int i = base * 256 + threadIdx.x;
    float v = src[i];
    bf16 h = __float2bfloat16(v);
    hi[i] = h;
    lo[i] = __float2bfloat16(v - __bfloat162float(h));
}

// ======== qkv projection body (dynamic smem) ========
__device__ void qkv_body(bf16* sm, int zz, int jt, int it) {
    const int BUF = 15360;
    const bf16 *Bh, *Bl; bf16 *Ch, *Cl;
    if (zz == 0)      { Bh = g_qwh; Bl = g_qwl; Ch = g_qh; Cl = g_ql; }
    else if (zz == 1) { Bh = g_kwh; Bl = g_kwl; Ch = g_kh; Cl = g_kl; }
    else              { Bh = g_vwh; Bl = g_vwl; Ch = g_vh; Cl = g_vl; }
    int tid = threadIdx.x, lane = tid & 31, w = tid >> 5;
    int m0 = it * 128, n0 = jt * 64;
    int arow = (w >> 1) * 32, bcol = (w & 1) * 32;
    float acc[2][4][4] = {};
    auto stg = [&](int b, int k0) {
        bf16* p = sm + b * BUF;
        stage2a(p, p+5120, 40, g_xh + (size_t)m0*1024 + k0, g_xl + (size_t)m0*1024 + k0, 1024, 128, 4, tid);
        stage2a(p+10240, p+12800, 40, Bh + (size_t)n0*1024 + k0, Bl + (size_t)n0*1024 + k0, 1024, 64, 4, tid);
        CPC();
    };
    stg(0, 0);
    for (int i = 0; i < 32; i++) {
        if (i+1 < 32) { stg((i+1)&1, (i+1)*32); CPW(1); } else CPW(0);
        __syncthreads();
        bf16* p = sm + (i&1)*BUF;
        mma_tile<false>(acc, p, p+5120, 40, arow, 0,  p+10240, p+12800, 40, bcol, 0,  lane);
        mma_tile<false>(acc, p, p+5120, 40, arow, 16, p+10240, p+12800, 40, bcol, 16, lane);
        __syncthreads();
    }
    int r0 = arow + (lane >> 2), c0 = bcol + (lane & 3) * 2;
#pragma unroll
    for (int mi = 0; mi < 2; mi++)
#pragma unroll
        for (int ni = 0; ni < 4; ni++)
#pragma unroll
            for (int hf = 0; hf < 2; hf++) {
                int row = m0 + r0 + mi*16 + hf*8;
                int col = n0 + c0 + ni*8;
                st_split2(Ch, Cl, (size_t)row * 1024 + col,
                          acc[mi][ni][hf*2], acc[mi][ni][hf*2+1]);
            }
}

// ======== lowrank body (dynamic smem) ========
__device__ void lowrank_body(float* dyn, int t,
    const float* __restrict__ x, const float* __restrict__ w1,
    const float* __restrict__ btw, const float* __restrict__ btb) {
    float* sx = dyn;            // 1024
    float* red = dyn + 1024;    // 64*5
    int tid = threadIdx.x;
    *(float4*)&sx[tid*4] = *(const float4*)&x[(size_t)t*1024 + tid*4];
    __syncthreads();
    int c = tid & 63, s = tid >> 6;
    const float* w = (c < 32) ? (w1 + (size_t)c*1024) : (btw + (size_t)(c-32)*1024);
    float acc = 0.f;
    for (int k = s*256; k < s*256 + 256; k += 4) {
        float4 wv = *(const float4*)&w[k];
        acc += wv.x*sx[k] + wv.y*sx[k+1] + wv.z*sx[k+2] + wv.w*sx[k+3];
    }
    red[c*5 + s] = acc;
    __syncthreads();
    if (tid < 64) {
        float v = red[tid*5] + red[tid*5+1] + red[tid*5+2] + red[tid*5+3];
        if (tid < 32) {
            bf16 hh = __float2bfloat16(v);
            g_wlh[t*32 + tid] = hh;
            g_wll[t*32 + tid] = __float2bfloat16(v - __bfloat162float(hh));
        } else {
            int hr = tid - 32;
            g_betah[hr*TT + t] = 2.f / (1.f + __expf(-(v + btb[hr])));
        }
    }
}

// ---- merged qkv + lowrank launch: z<3 qkv, z>=3 lowrank ----
__global__ __launch_bounds__(256)
void tc_qkv_lr(const float* __restrict__ x, const float* __restrict__ w1,
               const float* __restrict__ btw, const float* __restrict__ btb) {
    extern __shared__ __align__(16) bf16 sm[];
    int z = blockIdx.z;
    if (z < 3) qkv_body(sm, z, blockIdx.x, blockIdx.y);
    else {
        int t = (z - 3) * 128 + blockIdx.y * 16 + blockIdx.x;
        lowrank_body((float*)sm, t, x, w1, btw, btb);
    }
}

// ---- wraw = wlow @ w2^T on tensor cores ----
__global__ __launch_bounds__(256)
void tc_wraw() {
    __shared__ __align__(16) bf16 sA[15360];
    int tid = threadIdx.x, lane = tid & 31, w = tid >> 5;
    int m0 = blockIdx.y * 128, n0 = blockIdx.x * 64;
    int arow = (w >> 1) * 32, bcol = (w & 1) * 32;
    float acc[2][4][4] = {};
    stage2a(sA, sA+5120, 40, g_wlh + (size_t)m0*32, g_wll + (size_t)m0*32, 32, 128, 4, tid);
    stage2a(sA+10240, sA+12800, 40, g_w2h + (size_t)n0*32, g_w2l + (size_t)n0*32, 32, 64, 4, tid);
    CPC(); CPW(0);
    __syncthreads();
    mma_tile<false>(acc, sA, sA+5120, 40, arow, 0,  sA+10240, sA+12800, 40, bcol, 0,  lane);
    mma_tile<false>(acc, sA, sA+5120, 40, arow, 16, sA+10240, sA+12800, 40, bcol, 16, lane);
    int r0 = arow + (lane >> 2), c0 = bcol + (lane & 3) * 2;
#pragma unroll
    for (int mi = 0; mi < 2; mi++)
#pragma unroll
        for (int ni = 0; ni < 4; ni++)
#pragma unroll
            for (int hf = 0; hf < 2; hf++) {
                int row = m0 + r0 + mi*16 + hf*8;
                int col = n0 + c0 + ni*8;
                *(float2*)&g_wraw[(size_t)row * 4096 + col] =
                    make_float2(acc[mi][ni][hf*2], acc[mi][ni][hf*2+1]);
            }
}

// ---- dense out-projection ----
__global__ __launch_bounds__(256)
void tc_dense(const bf16* __restrict__ Ah, const bf16* __restrict__ Al, int lda,
              const bf16* __restrict__ Bh, const bf16* __restrict__ Bl, int ldb,
              int K, float* __restrict__ Cf, int ldc)
{
    extern __shared__ __align__(16) bf16 sm[];
    const int BUF = 15360;
    int tid = threadIdx.x, lane = tid & 31, w = tid >> 5;
    int m0 = blockIdx.y * 128, n0 = blockIdx.x * 64;
    int arow = (w >> 1) * 32, bcol = (w & 1) * 32;
    float acc[2][4][4] = {};
    int nk = K / 32;
    auto stg = [&](int b, int k0) {
        bf16* p = sm + b * BUF;
        stage2a(p, p+5120, 40, Ah + (size_t)m0*lda + k0, Al + (size_t)m0*lda + k0, lda, 128, 4, tid);
        stage2a(p+10240, p+12800, 40, Bh + (size_t)n0*ldb + k0, Bl + (size_t)n0*ldb + k0, ldb, 64, 4, tid);
        CPC();
    };
    stg(0, 0);
    for (int i = 0; i < nk; i++) {
        if (i+1 < nk) { stg((i+1)&1, (i+1)*32); CPW(1); } else CPW(0);
        __syncthreads();
        bf16* p = sm + (i&1)*BUF;
        mma_tile<false>(acc, p, p+5120, 40, arow, 0,  p+10240, p+12800, 40, bcol, 0,  lane);
        mma_tile<false>(acc, p, p+5120, 40, arow, 16, p+10240, p+12800, 40, bcol, 16, lane);
        __syncthreads();
    }
    int r0 = arow + (lane >> 2), c0 = bcol + (lane & 3) * 2;
#pragma unroll
    for (int mi = 0; mi < 2; mi++)
#pragma unroll
        for (int ni = 0; ni < 4; ni++)
#pragma unroll
            for (int hf = 0; hf < 2; hf++) {
                int row = m0 + r0 + mi*16 + hf*8;
                int col = n0 + c0 + ni*8;
                *(float2*)&Cf[(size_t)row * ldc + col] =
                    make_float2(acc[mi][ni][hf*2], acc[mi][ni][hf*2+1]);
            }
}

// ======== per-head GEMM body (stages 0..3), dynamic smem ========
__device__ void headz_body(bf16* sm, int stage, int h, int jt, int it) {
    const bf16 *Ahp, *Alp, *Bhp, *Blp;
    int lda, ldb, mode;
    const float* rowscale = nullptr;
    if (stage == 0) {
        Ahp = g_wdh + (size_t)h*65536; Alp = g_wdl + (size_t)h*65536; lda = 64;
        Bhp = g_wdh + (size_t)h*65536; Blp = g_wdl + (size_t)h*65536; ldb = 64;
        mode = 1; rowscale = g_betah;
    } else if (stage == 1) {
        Ahp = g_wdh + (size_t)h*65536; Alp = g_wdl + (size_t)h*65536; lda = 64;
        Bhp = g_kh + (size_t)(h>>1)*64; Blp = g_kl + (size_t)(h>>1)*64; ldb = 1024;
        mode = 1; rowscale = g_betah;
    } else if (stage == 2) {
        Ahp = g_qh + (size_t)h*64; Alp = g_ql + (size_t)h*64; lda = 1024;
        Bhp = g_kh + (size_t)h*64; Blp = g_kl + (size_t)h*64; ldb = 1024;
        mode = 2;
    } else {
        Ahp = g_qh + (size_t)(h>>1)*64; Alp = g_ql + (size_t)(h>>1)*64; lda = 1024;
        Bhp = g_wdh + (size_t)h*65536; Blp = g_wdl + (size_t)h*65536; ldb = 64;
        mode = 2;
    }
    Ahp += (size_t)(it*128) * lda; Alp += (size_t)(it*128) * lda;
    Bhp += (size_t)(jt*64)  * ldb; Blp += (size_t)(jt*64)  * ldb;

    const int BUF = 15360;
    int tid = threadIdx.x, lane = tid & 31, w = tid >> 5;
    int arow = (w >> 1) * 32, bcol = (w & 1) * 32;
    float acc[2][4][4] = {};
    auto stg = [&](int b, int k0) {
        bf16* p = sm + b * BUF;
        stage2a(p, p+5120, 40, Ahp + k0, Alp + k0, lda, 128, 4, tid);
        stage2a(p+10240, p+12800, 40, Bhp + k0, Blp + k0, ldb, 64, 4, tid);
        CPC();
    };
    stg(0, 0);
#pragma unroll
    for (int i = 0; i < 2; i++) {
        if (i == 0) { stg(1, 32); CPW(1); } else CPW(0);
        __syncthreads();
        bf16* p = sm + i*BUF;
        mma_tile<false>(acc, p, p+5120, 40, arow, 0,  p+10240, p+12800, 40, bcol, 0,  lane);
        mma_tile<false>(acc, p, p+5120, 40, arow, 16, p+10240, p+12800, 40, bcol, 16, lane);
        __syncthreads();
    }
    int r0 = arow + (lane >> 2), c0 = bcol + (lane & 3) * 2;
    size_t hb = (size_t)h * HS;
#pragma unroll
    for (int mi = 0; mi < 2; mi++)
#pragma unroll
        for (int ni = 0; ni < 4; ni++)
#pragma unroll
            for (int hf = 0; hf < 2; hf++) {
                int row = it*128 + r0 + mi*16 + hf*8;
                int col = jt*64 + c0 + ni*8;
                float v0 = acc[mi][ni][hf*2], v1 = acc[mi][ni][hf*2+1];
                float sc = rowscale ? rowscale[h * TT + row] : 1.f;
                v0 *= sc; v1 *= sc;
                if (mode == 1) { if (col   >= row) v0 = 0.f;
                                 if (col+1 >= row) v1 = 0.f; }
                else           { if (col   >  row) v0 = 0.f;
                                 if (col+1 >  row) v1 = 0.f; }
                size_t off = hb + (size_t)row * TT + col;
                if (stage == 0)      st_split2(g_Mwh, g_Mwl, off, v0, v1);
                else if (stage == 1) *(float2*)&g_rhs[off] = make_float2(v0, v1);
                else if (stage == 2) *(float2*)&g_QK[off]  = make_float2(v0, v1);
                else                 st_split2(g_QWh, g_QWl, off, v0, v1);
            }
}

// ---- headz stages 0+1 (Mw, rhs): z<32 stage0, z<64 stage1 ----
__global__ __launch_bounds__(256)
void tc_headz01() {
    int jt = blockIdx.x, it = blockIdx.y, z = blockIdx.z;
    if (jt > 2 * it + 1) return;
    extern __shared__ __align__(16) bf16 sm[];
    int stage = (z < 32) ? 0 : 1;
    int h = (z < 32) ? z : z - 32;
    headz_body(sm, stage, h, jt, it);
}

__global__ __launch_bounds__(64)
void compute_tinv() {
    __shared__ float L[64][65];
    __shared__ float X[64][65];
    int ch = blockIdx.x, h = blockIdx.y, c = threadIdx.x;
    size_t base = (size_t)h * HS + (size_t)(ch*64) * TT + ch*64;
    for (int r = 0; r < 64; r++) {
        L[r][c] = __bfloat162float(g_Mwh[base + (size_t)r*TT + c]) +
                  __bfloat162float(g_Mwl[base + (size_t)r*TT + c]);
        X[r][c] = (r == c) ? 1.f : 0.f;
    }
    __syncthreads();
    for (int r = 1; r < 64; r++) {
        if (c < r) {
            float acc = 0.f;
            for (int s = c; s < r; s++) acc += L[r][s] * X[s][c];
            X[r][c] = -acc;
        }
        __syncthreads();
    }
    size_t ob = ((size_t)(h*16 + ch)) * 4096;
    for (int r = 0; r < 64; r++) {
        float v = X[r][c];
        bf16 hh = __float2bfloat16(v);
        g_Tvh[ob + r*64 + c] = hh;
        g_Tvl[ob + r*64 + c] = __float2bfloat16(v - __bfloat162float(hh));
    }
}

// ======== solve body (one column block, all chunks), dynamic smem ========
__device__ void solve_body(bf16* sm, int jb, int h) {
    const int BUF = 13824;
    int tid = threadIdx.x, lane = tid & 31, w = tid >> 5;
    int arow = (w >> 2) * 32, bcol = (w & 3) * 32;
    size_t hb = (size_t)h * HS;
    int r0 = arow + (lane >> 2), c0 = bcol + (lane & 3) * 2;

    for (int ci = 2*jb; ci < 16; ci++) {
        float acc[2][4][4];
#pragma unroll
        for (int mi = 0; mi < 2; mi++)
#pragma unroll
            for (int ni = 0; ni < 4; ni++)
#pragma unroll
                for (int hf = 0; hf < 2; hf++) {
                    float2 v = *(const float2*)&g_rhs[hb +
                        (size_t)(ci*64 + r0 + mi*16 + hf*8) * TT + jb*128 + c0 + ni*8];
                    acc[mi][ni][hf*2]   = -v.x;
                    acc[mi][ni][hf*2+1] = -v.y;
                }
        int nch = 2 * (ci - 2*jb);
        auto stg = [&](int b, int m) {
            int s = 2*jb + (m >> 1), kc = (m & 1) * 32;
            bf16* p = sm + b * BUF;
            stage2a(p, p+2560, 40,
                    g_Mwh + hb + (size_t)(ci*64)*TT + s*64 + kc,
                    g_Mwl + hb + (size_t)(ci*64)*TT + s*64 + kc, TT, 64, 4, tid);
            stage2a(p+5120, p+9472, 136,
                    g_Bh + hb + (size_t)(s*64 + kc)*TT + jb*128,
                    g_Bl + hb + (size_t)(s*64 + kc)*TT + jb*128, TT, 32, 16, tid);
            CPC();
        };
        if (nch > 0) stg(0, 0);
        for (int m = 0; m < nch; m++) {
            if (m+1 < nch) { stg((m+1)&1, m+1); CPW(1); } else CPW(0);
            __syncthreads();
            bf16* p = sm + (m&1)*BUF;
            mma_tile<true>(acc, p, p+2560, 40, arow, 0,  p+5120, p+9472, 136, bcol, 0,  lane);
            mma_tile<true>(acc, p, p+2560, 40, arow, 16, p+5120, p+9472, 136, bcol, 16, lane);
            __syncthreads();
        }
        bf16 *sPh = sm, *sPl = sm + 8704, *sTh = sm + 17408, *sTl = sm + 19968;
        __syncthreads();
#pragma unroll
        for (int mi = 0; mi < 2; mi++)
#pragma unroll
            for (int ni = 0; ni < 4; ni++)
#pragma unroll
                for (int hf = 0; hf < 2; hf++) {
                    int r = r0 + mi*16 + hf*8, c = c0 + ni*8;
                    st_split2(sPh, sPl, (size_t)r*136 + c,
                              -acc[mi][ni][hf*2], -acc[mi][ni][hf*2+1]);
                }
#pragma unroll
        for (int mi = 0; mi < 2; mi++)
#pragma unroll
            for (int ni = 0; ni < 4; ni++)
#pragma unroll
                for (int e = 0; e < 4; e++) acc[mi][ni][e] = 0.f;
        size_t tb = ((size_t)(h*16 + ci)) * 4096;
#pragma unroll
        for (int kc = 0; kc < 64; kc += 32) {
            stage2a(sTh, sTl, 40, g_Tvh + tb + kc, g_Tvl + tb + kc, 64, 64, 4, tid);
            CPC(); CPW(0);
            __syncthreads();
            mma_tile<true>(acc, sTh, sTl, 40, arow, 0,  sPh, sPl, 136, bcol, kc,      lane);
            mma_tile<true>(acc, sTh, sTl, 40, arow, 16, sPh, sPl, 136, bcol, kc + 16, lane);
            __syncthreads();
        }
#pragma unroll
        for (int mi = 0; mi < 2; mi++)
#pragma unroll
            for (int ni = 0; ni < 4; ni++)
#pragma unroll
                for (int hf = 0; hf < 2; hf++) {
                    int row = ci*64 + r0 + mi*16 + hf*8;
                    int col = jb*128 + c0 + ni*8;
                    st_split2(g_Bh, g_Bl, hb + (size_t)row*TT + col,
                              acc[mi][ni][hf*2], acc[mi][ni][hf*2+1]);
                }
        __syncthreads();
    }
}

// ---- merged launch: solve (z<2, scheduled first) + QK (z 2..17) + QW (z 18..49) ----
__global__ __launch_bounds__(256)
void tc_mix() {
    extern __shared__ __align__(16) bf16 sm[];
    int z = blockIdx.z;
    if (z < 2) {
        int idx = z * 128 + blockIdx.y * 16 + blockIdx.x;   // 0..255
        solve_body(sm, idx & 7, idx >> 3);
    } else {
        int jt = blockIdx.x, it = blockIdx.y;
        if (jt > 2 * it + 1) return;
        int zz = z - 2;
        int stage = (zz < 16) ? 2 : 3;
        int h = (zz < 16) ? zz : zz - 16;
        headz_body(sm, stage, h, jt, it);
    }
}

// ==== flash-fused attention: logits + online softmax + PV, split-K over jt ====
__global__ __launch_bounds__(128)
void tc_attn() {
    extern __shared__ __align__(16) bf16 sm[];
    const int BUF = 9728;
    bf16* sPh = sm + 19456;
    bf16* sPl = sm + 24064;
    float* sMrow = (float*)(sm + 28672);
    float* sSrow = sMrow + 64;
    float* sPmax = sSrow + 64;
    float* sPsum = sPmax + 128;
    int it = 15 - blockIdx.x, p = blockIdx.y, h = blockIdx.z;
    int tid = threadIdx.x, lane = tid & 31, w = tid >> 5;
    int arow = (w >> 1) * 32, bcol = (w & 1) * 32;
    int rl0 = arow + (lane >> 2), cl0 = bcol + (lane & 3) * 2;
    size_t hb = (size_t)h * HS;
    size_t qb = (size_t)(h >> 1) * HS;
    for (int i = tid; i < 64; i += 128) { sMrow[i] = -1e30f; sSrow[i] = 0.f; }
    float o[2][4][4];
#pragma unroll
    for (int mi = 0; mi < 2; mi++)
#pragma unroll
        for (int ni = 0; ni < 4; ni++)
#pragma unroll
            for (int e = 0; e < 4; e++) o[mi][ni][e] = 0.f;
    __syncthreads();

    for (int jt = p; jt <= it; jt += 2) {
        float acc[2][4][4] = {};
        int nch = 2 * (it - jt + 1);
        auto stg = [&](int b, int m) {
            int kb = jt + (m >> 1), kc = (m & 1) * 32;
            bf16* pp = sm + b * BUF;
            stage128(pp, pp+2560, 40,
                g_QWh + hb + (size_t)(it*64)*TT + kb*64 + kc,
                g_QWl + hb + (size_t)(it*64)*TT + kb*64 + kc, TT, 64, 4, tid);
            stage128(pp+5120, pp+7424, 72,
                g_Bh + hb + (size_t)(kb*64 + kc)*TT + jt*64,
                g_Bl + hb + (size_t)(kb*64 + kc)*TT + jt*64, TT, 32, 8, tid);
            CPC();
        };
        stg(0, 0);
        for (int m = 0; m < nch; m++) {
            if (m+1 < nch) { stg((m+1)&1, m+1); CPW(1); } else CPW(0);
            __syncthreads();
            bf16* pp = sm + (m&1)*BUF;
            mma_tile<true>(acc, pp, pp+2560, 40, arow, 0,  pp+5120, pp+7424, 72, bcol, 0,  lane);
            mma_tile<true>(acc, pp, pp+2560, 40, arow, 16, pp+5120, pp+7424, 72, bcol, 16, lane);
            __syncthreads();
        }
        float pmv[2][2];
#pragma unroll
        for (int mi = 0; mi < 2; mi++)
#pragma unroll
            for (int hf = 0; hf < 2; hf++) {
                int rl = rl0 + mi*16 + hf*8;
                int row_g = it*64 + rl;
                float best = -1e30f;
#pragma unroll
                for (int ni = 0; ni < 4; ni++) {
                    int col_g = jt*64 + cl0 + ni*8;
                    float2 q = *(const float2*)&g_QK[qb + (size_t)row_g*TT + col_g];
                    float L0 = (q.x - acc[mi][ni][hf*2])   * ATT_SCALE;
                    float L1 = (q.y - acc[mi][ni][hf*2+1]) * ATT_SCALE;
                    if (jt == it) {
                        if (col_g     > row_g) L0 = -1e30f;
                        if (col_g + 1 > row_g) L1 = -1e30f;
                    }
                    acc[mi][ni][hf*2]   = L0;
                    acc[mi][ni][hf*2+1] = L1;
                    best = fmaxf(best, fmaxf(L0, L1));
                }
                pmv[mi][hf] = best;
            }
#pragma unroll
        for (int mi = 0; mi < 2; mi++)
#pragma unroll
            for (int hf = 0; hf < 2; hf++) {
                float v = pmv[mi][hf];
                v = fmaxf(v, __shfl_xor_sync(~0u, v, 1));
                v = fmaxf(v, __shfl_xor_sync(~0u, v, 2));
                pmv[mi][hf] = v;
            }
        if ((lane & 3) == 0)
#pragma unroll
            for (int mi = 0; mi < 2; mi++)
#pragma unroll
                for (int hf = 0; hf < 2; hf++)
                    sPmax[(rl0 + mi*16 + hf*8)*2 + (w & 1)] = pmv[mi][hf];
        __syncthreads();
        float psv[2][2];
#pragma unroll
        for (int mi = 0; mi < 2; mi++)
#pragma unroll
            for (int hf = 0; hf < 2; hf++) {
                int rl = rl0 + mi*16 + hf*8;
                float mo = sMrow[rl];
                float m2 = fmaxf(mo, fmaxf(sPmax[rl*2], sPmax[rl*2+1]));
                float f = __expf(mo - m2);
                float sum = 0.f;
#pragma unroll
                for (int ni = 0; ni < 4; ni++) {
                    float e0 = __expf(acc[mi][ni][hf*2]   - m2);
                    float e1 = __expf(acc[mi][ni][hf*2+1] - m2);
                    acc[mi][ni][hf*2] = e0; acc[mi][ni][hf*2+1] = e1;
                    sum += e0 + e1;
                    o[mi][ni][hf*2]   *= f;
                    o[mi][ni][hf*2+1] *= f;
                    st_split2(sPh, sPl, (size_t)rl*72 + cl0 + ni*8, e0, e1);
                }
                psv[mi][hf] = sum;
            }
#pragma unroll
        for (int mi = 0; mi < 2; mi++)
#pragma unroll
            for (int hf = 0; hf < 2; hf++) {
                float v = psv[mi][hf];
                v += __shfl_xor_sync(~0u, v, 1);
                v += __shfl_xor_sync(~0u, v, 2);
                psv[mi][hf] = v;
            }
        if ((lane & 3) == 0)
#pragma unroll
            for (int mi = 0; mi < 2; mi++)
#pragma unroll
                for (int hf = 0; hf < 2; hf++)
                    sPsum[(rl0 + mi*16 + hf*8)*2 + (w & 1)] = psv[mi][hf];
        stage128(sm, sm + 4608, 72,
                 g_vh + (size_t)(jt*64)*1024 + (size_t)(h>>1)*64,
                 g_vl + (size_t)(jt*64)*1024 + (size_t)(h>>1)*64, 1024, 64, 8, tid);
        CPC();
        __syncthreads();
        if (tid < 64) {
            float mo = sMrow[tid];
            float m2 = fmaxf(mo, fmaxf(sPmax[tid*2], sPmax[tid*2+1]));
            float f = __expf(mo - m2);
            sSrow[tid] = sSrow[tid] * f + sPsum[tid*2] + sPsum[tid*2+1];
            sMrow[tid] = m2;
        }
        CPW(0);
        __syncthreads();
#pragma unroll
        for (int mi = 0; mi < 2; mi++)
#pragma unroll
            for (int ni = 0; ni < 4; ni++)
#pragma unroll
                for (int e = 0; e < 4; e++) acc[mi][ni][e] = 0.f;
        mma_tile<true>(acc, sPh, sPl, 72, arow, 0,  sm, sm+4608, 72, bcol, 0,  lane);
        mma_tile<true>(acc, sPh, sPl, 72, arow, 16, sm, sm+4608, 72, bcol, 16, lane);
        mma_tile<true>(acc, sPh, sPl, 72, arow, 32, sm, sm+4608, 72, bcol, 32, lane);
        mma_tile<true>(acc, sPh, sPl, 72, arow, 48, sm, sm+4608, 72, bcol, 48, lane);
#pragma unroll
        for (int mi = 0; mi < 2; mi++)
#pragma unroll
            for (int ni = 0; ni < 4; ni++)
#pragma unroll
                for (int e = 0; e < 4; e++) o[mi][ni][e] += acc[mi][ni][e];
        __syncthreads();
    }
    float* PB = g_rhs + ((size_t)((h*16 + it)*2 + p)) * 4224;
#pragma unroll
    for (int mi = 0; mi < 2; mi++)
#pragma unroll
        for (int ni = 0; ni < 4; ni++)
#pragma unroll
            for (int hf = 0; hf < 2; hf++) {
                int rl = rl0 + mi*16 + hf*8;
                *(float2*)&PB[rl*64 + cl0 + ni*8] =
                    make_float2(o[mi][ni][hf*2], o[mi][ni][hf*2+1]);
            }
    if (tid < 64) { PB[4096 + tid] = sMrow[tid]; PB[4160 + tid] = sSrow[tid]; }
}

__global__ __launch_bounds__(128)
void attn_merge() {
    int it = blockIdx.x, h = blockIdx.y, tid = threadIdx.x;
    const float* P0 = g_rhs + ((size_t)((h*16 + it)*2)) * 4224;
    const float* P1 = P0 + 4224;
    __shared__ float w0[64], w1[64], inv[64];
    if (tid < 64) {
        float m0 = P0[4096+tid], m1 = P1[4096+tid];
        float mm = fmaxf(m0, m1);
        float e0 = __expf(m0 - mm), e1 = __expf(m1 - mm);
        float s = P0[4160+tid]*e0 + P1[4160+tid]*e1;
        w0[tid] = e0; w1[tid] = e1; inv[tid] = 1.f / s;
    }
    __syncthreads();
    for (int i = tid; i < 4096; i += 128) {
        int r = i >> 6, c = i & 63;
        float v = (P0[i]*w0[r] + P1[i]*w1[r]) * inv[r];
        size_t off = (size_t)(it*64 + r) * 2048 + h*64 + c;
        bf16 hh = __float2bfloat16(v);
        g_O2h[off] = hh;
        g_O2l[off] = __float2bfloat16(v - __bfloat162float(hh));
    }
}

__global__ __launch_bounds__(64)
void wdir_kernel(const float* __restrict__ wraw, const float* __restrict__ conv_w,
                 const float* __restrict__ omega, const float* __restrict__ phi) {
    int t = blockIdx.x, hr = blockIdx.y, d = threadIdx.x;
    int hkv = hr >> 1, r = hr & 1;
    int cA = hkv * 256 + (2*r) * 64 + d;
    int cB = cA + 64;
    float a = 0.f, b = 0.f;
#pragma unroll
    for (int i = 0; i < 3; i++) {
        int tt = t + i - 2;
        if (tt >= 0) {
            a += wraw[(size_t)tt * 4096 + cA] * conv_w[cA*3 + i];
            b += wraw[(size_t)tt * 4096 + cB] * conv_w[cB*3 + i];
        }
    }
    a = a / (1.f + expf(-a));
    b = b / (1.f + expf(-b));
    float th = omega[r] * (float)t + phi[r];
    float w = a * cosf(th) + b * sinf(th);
    float ss = w * w;
#pragma unroll
    for (int o = 16; o; o >>= 1) ss += __shfl_xor_sync(~0u, ss, o);
    __shared__ float sh[2];
    if ((d & 31) == 0) sh[d >> 5] = ss;
    __syncthreads();
    float tot = sh[0] + sh[1];
    float val = w * rsqrtf(tot + 1e-6f);
    size_t off = ((size_t)hr * TT + t) * 64 + d;
    bf16 hh = __float2bfloat16(val);
    g_wdh[off] = hh;
    g_wdl[off] = __float2bfloat16(val - __bfloat162float(hh));
}

#define GS(p, s) cudaGetSymbolAddress((void**)&p, s)

extern "C" void kernel_launch(void* const* d_in, const int* in_sizes, int n_in,
                              void* d_out, int out_size) {
    const float* x    = (const float*)d_in[0];
    const float* q_w  = (const float*)d_in[1];
    const float* k_w  = (const float*)d_in[2];
    const float* v_w  = (const float*)d_in[3];
    const float* w1   = (const float*)d_in[4];
    const float* w2   = (const float*)d_in[5];
    const float* cw   = (const float*)d_in[6];
    const float* btw  = (const float*)d_in[7];
    const float* btb  = (const float*)d_in[8];
    const float* ow   = (const float*)d_in[9];
    const float* omega= (const float*)d_in[10];
    const float* phi  = (const float*)d_in[11];
    float* out = (float*)d_out;

    float* pwraw;
    bf16 *pO2h,*pO2l,*powh,*powl;
    GS(pwraw,g_wraw);
    GS(pO2h,g_O2h); GS(pO2l,g_O2l); GS(powh,g_owh); GS(powl,g_owl);

    static bool attr_done = false;
    if (!attr_done) {
        cudaFuncSetAttribute(tc_dense,   cudaFuncAttributeMaxDynamicSharedMemorySize, 61440);
        cudaFuncSetAttribute(tc_qkv_lr,  cudaFuncAttributeMaxDynamicSharedMemorySize, 61440);
        cudaFuncSetAttribute(tc_headz01, cudaFuncAttributeMaxDynamicSharedMemorySize, 61440);
        cudaFuncSetAttribute(tc_mix,     cudaFuncAttributeMaxDynamicSharedMemorySize, 61440);
        cudaFuncSetAttribute(tc_attn,    cudaFuncAttributeMaxDynamicSharedMemorySize, 58880);
        attr_done = true;
    }

    split_all<<<25088, 256>>>(x, q_w, k_w, v_w, ow, w2);

    // qkv (z<3) merged with lowrank (z 3..10)
    tc_qkv_lr<<<dim3(16,8,11), 256, 61440>>>(x, w1, btw, btb);
    tc_wraw<<<dim3(64,8), 256>>>();
    wdir_kernel<<<dim3(1024, 32), 64>>>(pwraw, cw, omega, phi);

    // Mw + rhs
    tc_headz01<<<dim3(16,8,64), 256, 61440>>>();
    compute_tinv<<<dim3(16,32), 64>>>();

    // merged: solve (z<2) + QK (z 2..17) + QW (z 18..49)
    tc_mix<<<dim3(16,8,50), 256, 61440>>>();

    tc_attn<<<dim3(16,2,32), 128, 58880>>>();
    attn_merge<<<dim3(16,32), 128>>>();

    tc_dense<<<dim3(16,8), 256, 61440>>>(pO2h, pO2l, 2048, powh, powl, 2048, 2048,
                                         out, 1024);
}